// round 1
// baseline (speedup 1.0000x reference)
#include <cuda_runtime.h>
#include <math.h>

// ---------------- problem constants ----------------
#define B_        16
#define C_        512
#define H_        16
#define W_        300
#define HO_       10
#define KG_       10          // K + G cluster channels
#define KC_       8           // K clusters kept
#define OUT_      5994
#define KDIM      3584        // C_ * 7
#define NDIM      48000       // B_ * HO_ * W_
#define MPAD      576
#define MREAL     522
#define HWX       4800        // H_*W_
#define BSTR      2457600     // C_*H_*W_
#define P_        3000        // HO_*W_
#define FEAT_BSTR 1536000     // C_*P_
#define SCOR_BSTR 30000       // KG_*P_

// ---------------- device scratch (no runtime alloc allowed) ----------------
__device__ float g_wpack[MPAD * KDIM];          // packed conv_w||cc_w, zero padded
__device__ float g_bias[MPAD];
__device__ float g_feats[B_ * C_ * HO_ * W_];   // relu(conv) output
__device__ float g_scores[B_ * KG_ * HO_ * W_];
__device__ float g_assign[B_ * KG_ * HO_ * W_];
__device__ float g_asum[B_ * KC_];
__device__ float g_agg[B_ * KC_ * C_];
__device__ float g_vlad[B_ * KC_ * C_];

// ---------------- K0: pack weights + biases ----------------
__global__ void pack_kernel(const float* __restrict__ conv_w,
                            const float* __restrict__ conv_b,
                            const float* __restrict__ cc_w,
                            const float* __restrict__ cc_b) {
    int i = blockIdx.x * blockDim.x + threadIdx.x;
    if (i < MPAD * KDIM) {
        int r = i / KDIM, k = i - r * KDIM;
        float v = 0.f;
        if (r < 512)       v = conv_w[r * KDIM + k];
        else if (r < 522)  v = cc_w[(r - 512) * KDIM + k];
        g_wpack[i] = v;
    }
    if (i < MPAD) {
        float bv = 0.f;
        if (i < 512)       bv = conv_b[i];
        else if (i < 522)  bv = cc_b[i - 512];
        g_bias[i] = bv;
    }
}

// ---------------- K1: fused conv+cc implicit GEMM ----------------
// C[m][n] = sum_k W[m][k] * X[n-patch][k],  m in [0,522), n=(b,ho,w), k=(ci,kh)
// BM=64, BN=128, BK=16, 128 threads, 8x8 per thread, reg-prefetch double buffer.
__global__ __launch_bounds__(128) void conv_gemm(const float* __restrict__ x) {
    __shared__ __align__(16) float As[16][68];   // [kk][m] transposed, +4 pad
    __shared__ __align__(16) float Bs[16][128];  // [kk][n]

    const int tid = threadIdx.x;
    const int tx  = tid & 15;   // n dim (16)
    const int ty  = tid >> 4;   // m dim (8)
    const int nBase = blockIdx.x * 128;
    const int mBase = blockIdx.y * 64;

    // per-thread B column base offset into x (n = nBase + tid)
    const int n   = nBase + tid;
    const int bb  = n / P_;
    const int rem = n - bb * P_;
    const int ho  = rem / W_;
    const int w   = rem - ho * W_;
    const long offn = (long)bb * BSTR + (long)ho * W_ + w;

    // per-thread A load slot: row tid>>1, k-offset (tid&1)*8
    const int arow  = tid >> 1;
    const int akoff = (tid & 1) * 8;
    const float* aBase = &g_wpack[(mBase + arow) * KDIM + akoff];

    float acc[8][8];
#pragma unroll
    for (int i = 0; i < 8; i++)
#pragma unroll
        for (int j = 0; j < 8; j++) acc[i][j] = 0.f;

    float aReg[8], bReg[16];

    // ---- prologue: tile k0 = 0 ----
    {
        float4 a0 = *(const float4*)(aBase);
        float4 a1 = *(const float4*)(aBase + 4);
        aReg[0]=a0.x; aReg[1]=a0.y; aReg[2]=a0.z; aReg[3]=a0.w;
        aReg[4]=a1.x; aReg[5]=a1.y; aReg[6]=a1.z; aReg[7]=a1.w;
#pragma unroll
        for (int kk = 0; kk < 16; kk++) {
            int k  = kk;
            int ci = k / 7;
            int kh = k - ci * 7;
            bReg[kk] = x[offn + (long)ci * HWX + kh * W_];
        }
#pragma unroll
        for (int i = 0; i < 8; i++) As[akoff + i][arow] = aReg[i];
#pragma unroll
        for (int kk = 0; kk < 16; kk++) Bs[kk][tid] = bReg[kk];
    }
    __syncthreads();

    for (int k0 = 0; k0 < KDIM; k0 += 16) {
        const bool hasNext = (k0 + 16) < KDIM;
        if (hasNext) {
            const float* ap2 = aBase + (k0 + 16);
            float4 a0 = *(const float4*)(ap2);
            float4 a1 = *(const float4*)(ap2 + 4);
            aReg[0]=a0.x; aReg[1]=a0.y; aReg[2]=a0.z; aReg[3]=a0.w;
            aReg[4]=a1.x; aReg[5]=a1.y; aReg[6]=a1.z; aReg[7]=a1.w;
#pragma unroll
            for (int kk = 0; kk < 16; kk++) {
                int k  = k0 + 16 + kk;
                int ci = k / 7;
                int kh = k - ci * 7;
                bReg[kk] = x[offn + (long)ci * HWX + kh * W_];
            }
        }
        // ---- compute on current smem tile ----
#pragma unroll
        for (int kk = 0; kk < 16; kk++) {
            float4 a0 = *(const float4*)&As[kk][ty * 4];
            float4 a1 = *(const float4*)&As[kk][32 + ty * 4];
            float4 b0 = *(const float4*)&Bs[kk][tx * 4];
            float4 b1 = *(const float4*)&Bs[kk][64 + tx * 4];
            float a[8] = {a0.x,a0.y,a0.z,a0.w,a1.x,a1.y,a1.z,a1.w};
            float b[8] = {b0.x,b0.y,b0.z,b0.w,b1.x,b1.y,b1.z,b1.w};
#pragma unroll
            for (int i = 0; i < 8; i++)
#pragma unroll
                for (int j = 0; j < 8; j++)
                    acc[i][j] = fmaf(a[i], b[j], acc[i][j]);
        }
        __syncthreads();
        if (hasNext) {
#pragma unroll
            for (int i = 0; i < 8; i++) As[akoff + i][arow] = aReg[i];
#pragma unroll
            for (int kk = 0; kk < 16; kk++) Bs[kk][tid] = bReg[kk];
            __syncthreads();
        }
    }

    // ---- epilogue: bias, relu on conv rows, scatter to feats/scores ----
    float bias_i[8];
#pragma unroll
    for (int i = 0; i < 8; i++) {
        int mg = mBase + ((i < 4) ? (ty * 4 + i) : (32 + ty * 4 + i - 4));
        bias_i[i] = g_bias[mg];
    }
#pragma unroll
    for (int j = 0; j < 8; j++) {
        int nj  = nBase + ((j < 4) ? (tx * 4 + j) : (64 + tx * 4 + j - 4));
        int bb2 = nj / P_;
        int r2  = nj - bb2 * P_;
        int ho2 = r2 / W_;
        int w2  = r2 - ho2 * W_;
        int fbase = bb2 * FEAT_BSTR + ho2 * W_ + w2;
        int sbase = bb2 * SCOR_BSTR + ho2 * W_ + w2;
#pragma unroll
        for (int i = 0; i < 8; i++) {
            int mg = mBase + ((i < 4) ? (ty * 4 + i) : (32 + ty * 4 + i - 4));
            float v = acc[i][j] + bias_i[i];
            if (mg < 512) {
                g_feats[fbase + mg * P_] = fmaxf(v, 0.f);
            } else if (mg < MREAL) {
                g_scores[sbase + (mg - 512) * P_] = v;
            }
        }
    }
}

// ---------------- K2: softmax over 10 cluster channels ----------------
__global__ void softmax_kernel() {
    int q = blockIdx.x * 256 + threadIdx.x;
    if (q >= NDIM) return;
    int b   = q / P_;
    int rem = q - b * P_;               // ho*300 + w
    int base = b * SCOR_BSTR + rem;
    float s[KG_];
    float mx = -1e30f;
#pragma unroll
    for (int k = 0; k < KG_; k++) { s[k] = g_scores[base + k * P_]; mx = fmaxf(mx, s[k]); }
    float sum = 0.f;
#pragma unroll
    for (int k = 0; k < KG_; k++) { s[k] = expf(s[k] - mx); sum += s[k]; }
    float inv = 1.f / sum;
#pragma unroll
    for (int k = 0; k < KG_; k++) g_assign[base + k * P_] = s[k] * inv;
}

// ---------------- K2b: asum (only k < 8 needed) ----------------
__global__ void asum_kernel() {
    int b = blockIdx.x >> 3, k = blockIdx.x & 7;
    const float* a = g_assign + b * SCOR_BSTR + k * P_;
    float s = 0.f;
    for (int i = threadIdx.x; i < P_; i += 256) s += a[i];
    __shared__ float red[256];
    red[threadIdx.x] = s;
    __syncthreads();
    for (int st = 128; st > 0; st >>= 1) {
        if (threadIdx.x < st) red[threadIdx.x] += red[threadIdx.x + st];
        __syncthreads();
    }
    if (threadIdx.x == 0) g_asum[blockIdx.x] = red[0];
}

// ---------------- K3: agg[b][k][c] = sum_p assign[b][k][p] * feats[b][c][p], k<8 ----
__global__ void agg_kernel() {
    __shared__ float fs[64][65];
    __shared__ float as[8][64];
    const int b  = blockIdx.y;
    const int c0 = blockIdx.x * 64;
    const int t  = threadIdx.x;       // 256
    const int k  = t >> 6;            // 0..3 (pairs with k+4)
    const int c  = t & 63;
    const float* fb = g_feats  + (long)b * FEAT_BSTR + (long)c0 * P_;
    const float* ab = g_assign + b * SCOR_BSTR;
    float acc0 = 0.f, acc1 = 0.f;

    for (int p0 = 0; p0 < P_; p0 += 64) {
        int pc = P_ - p0; if (pc > 64) pc = 64;
#pragma unroll
        for (int idx = t; idx < 4096; idx += 256) {
            int cc = idx >> 6, pp = idx & 63;
            fs[cc][pp] = (pp < pc) ? fb[cc * P_ + p0 + pp] : 0.f;
        }
#pragma unroll
        for (int idx = t; idx < 512; idx += 256) {
            int kk = idx >> 6, pp = idx & 63;
            as[kk][pp] = (pp < pc) ? ab[kk * P_ + p0 + pp] : 0.f;
        }
        __syncthreads();
#pragma unroll
        for (int p = 0; p < 64; p++) {
            float f = fs[c][p];
            acc0 = fmaf(as[k][p],     f, acc0);
            acc1 = fmaf(as[k + 4][p], f, acc1);
        }
        __syncthreads();
    }
    g_agg[b * 4096 + k * 512 + c0 + c]       = acc0;
    g_agg[b * 4096 + (k + 4) * 512 + c0 + c] = acc1;
}

// ---------------- K4: cluster residual + L2 normalize -> vlad ----------------
__global__ void vlad_kernel(const float* __restrict__ centroids) {
    const int b = blockIdx.x >> 3, k = blockIdx.x & 7;
    const int t = threadIdx.x;      // 256, 2 channels each
    const float asum = g_asum[blockIdx.x];
    const float* aggp = g_agg + b * 4096 + k * 512;
    const float* cen  = centroids + k * 512;
    float r0 = aggp[t]       - asum * cen[t];
    float r1 = aggp[t + 256] - asum * cen[t + 256];
    __shared__ float red[256];
    red[t] = r0 * r0 + r1 * r1;
    __syncthreads();
    for (int st = 128; st > 0; st >>= 1) {
        if (t < st) red[t] += red[t + st];
        __syncthreads();
    }
    __shared__ float scale_s;
    if (t == 0) scale_s = 1.f / fmaxf(sqrtf(red[0]), 1e-12f);
    __syncthreads();
    float sc = scale_s;
    g_vlad[b * 4096 + k * 512 + t]       = r0 * sc;
    g_vlad[b * 4096 + k * 512 + t + 256] = r1 * sc;
}

// ---------------- K5: emb = relu(vlad @ fc_w^T + fc_b) ----------------
__global__ void emb_kernel(const float* __restrict__ fc_w,
                           const float* __restrict__ fc_b,
                           float* __restrict__ out) {
    const int b = blockIdx.y, co = blockIdx.x;
    const float4* v  = (const float4*)(g_vlad + b * 4096);
    const float4* wr = (const float4*)(fc_w + (long)co * 4096);
    float s = 0.f;
    for (int i = threadIdx.x; i < 1024; i += 128) {
        float4 a = v[i], w4 = wr[i];
        s += a.x * w4.x + a.y * w4.y + a.z * w4.z + a.w * w4.w;
    }
    __shared__ float red[128];
    red[threadIdx.x] = s;
    __syncthreads();
    for (int st = 64; st > 0; st >>= 1) {
        if (threadIdx.x < st) red[threadIdx.x] += red[threadIdx.x + st];
        __syncthreads();
    }
    if (threadIdx.x == 0)
        out[b * 512 + co] = fmaxf(red[0] + fc_b[co], 0.f);
}

// ---------------- K6: logit = emb @ logit_w^T ----------------
__global__ void logit_kernel(const float* __restrict__ emb,
                             const float* __restrict__ lw,
                             float* __restrict__ out) {
    const int b = blockIdx.y, o = blockIdx.x;
    const float4* e  = (const float4*)(emb + b * 512);
    const float4* wr = (const float4*)(lw + (long)o * 512);
    float s = 0.f;
    for (int i = threadIdx.x; i < 128; i += 64) {
        float4 a = e[i], w4 = wr[i];
        s += a.x * w4.x + a.y * w4.y + a.z * w4.z + a.w * w4.w;
    }
    __shared__ float red[64];
    red[threadIdx.x] = s;
    __syncthreads();
    for (int st = 32; st > 0; st >>= 1) {
        if (threadIdx.x < st) red[threadIdx.x] += red[threadIdx.x + st];
        __syncthreads();
    }
    if (threadIdx.x == 0) out[b * OUT_ + o] = red[0];
}

// ---------------- launch ----------------
extern "C" void kernel_launch(void* const* d_in, const int* in_sizes, int n_in,
                              void* d_out, int out_size) {
    const float* x5        = (const float*)d_in[0];
    const float* conv_w    = (const float*)d_in[5];
    const float* conv_b    = (const float*)d_in[6];
    const float* cc_w      = (const float*)d_in[7];
    const float* cc_b      = (const float*)d_in[8];
    const float* centroids = (const float*)d_in[9];
    const float* fc_w      = (const float*)d_in[10];
    const float* fc_b      = (const float*)d_in[11];
    const float* logit_w   = (const float*)d_in[12];
    float* out = (float*)d_out;

    pack_kernel<<<(MPAD * KDIM + 255) / 256, 256>>>(conv_w, conv_b, cc_w, cc_b);
    conv_gemm<<<dim3(NDIM / 128, MPAD / 64), 128>>>(x5);
    softmax_kernel<<<(NDIM + 255) / 256, 256>>>();
    asum_kernel<<<B_ * KC_, 256>>>();
    agg_kernel<<<dim3(8, B_), 256>>>();
    vlad_kernel<<<B_ * KC_, 256>>>(centroids);
    emb_kernel<<<dim3(C_, B_), 128>>>(fc_w, fc_b, out);
    logit_kernel<<<dim3(OUT_, B_), 64>>>(out, logit_w, out + B_ * C_);
}

// round 3
// speedup vs baseline: 1.6552x; 1.6552x over previous
#include <cuda_runtime.h>
#include <cuda_bf16.h>
#include <cstdint>
#include <math.h>

// ---------------- problem constants ----------------
#define B_        16
#define C_        512
#define H_        16
#define W_        300
#define HO_       10
#define KG_       10
#define KC_       8
#define OUT_      5994
#define KDIM      3584        // C_ * 7
#define NDIM      48000       // B_ * HO_ * W_
#define MPAD      640         // 5 x 128 M-tiles (522 real rows)
#define MREAL     522
#define HWX       4800        // H_*W_
#define BSTR      2457600     // C_*H_*W_
#define P_        3000        // HO_*W_
#define FEAT_BSTR 1536000     // C_*P_
#define SCOR_BSTR 30000       // KG_*P_
#define XT_ROWS   (B_*H_*W_)  // 76800

// GEMM tiling
#define MT        128
#define NT        128
#define KC_CHUNK  32
#define NCHUNK    112         // KDIM / 32
#define ROWB      80          // padded smem row stride in bytes (32 bf16 + pad)
#define TILE_B    10240       // 128 rows * 80B
#define BUF_B     40960       // AHI|ALO|BHI|BLO
#define SMEM_TOTAL (2*BUF_B)  // 81920

// ---------------- device scratch ----------------
__device__ __nv_bfloat16 g_wh[MPAD * KDIM];
__device__ __nv_bfloat16 g_wl[MPAD * KDIM];
__device__ float g_bias[MPAD];
__device__ __nv_bfloat16 g_xhi[XT_ROWS * C_];
__device__ __nv_bfloat16 g_xlo[XT_ROWS * C_];
__device__ float g_feats[B_ * C_ * HO_ * W_];
__device__ float g_scores[B_ * KG_ * HO_ * W_];
__device__ float g_assign[B_ * KG_ * HO_ * W_];
__device__ float g_asum[B_ * KC_];
__device__ float g_agg[B_ * KC_ * C_];
__device__ float g_vlad[B_ * KC_ * C_];

// ---------------- helpers ----------------
__device__ __forceinline__ uint32_t smem_u32(const void* p) {
    uint32_t a;
    asm("{ .reg .u64 t; cvta.to.shared.u64 t, %1; cvt.u32.u64 %0, t; }" : "=r"(a) : "l"(p));
    return a;
}
__device__ __forceinline__ void ldsm4(uint32_t* r, uint32_t addr) {
    asm volatile("ldmatrix.sync.aligned.m8n8.x4.shared.b16 {%0,%1,%2,%3}, [%4];"
                 : "=r"(r[0]), "=r"(r[1]), "=r"(r[2]), "=r"(r[3]) : "r"(addr));
}
__device__ __forceinline__ void mma_bf16(float* c, const uint32_t* a, const uint32_t* b) {
    asm volatile(
        "mma.sync.aligned.m16n8k16.row.col.f32.bf16.bf16.f32 "
        "{%0,%1,%2,%3},{%4,%5,%6,%7},{%8,%9},{%0,%1,%2,%3};"
        : "+f"(c[0]), "+f"(c[1]), "+f"(c[2]), "+f"(c[3])
        : "r"(a[0]), "r"(a[1]), "r"(a[2]), "r"(a[3]), "r"(b[0]), "r"(b[1]));
}

// ---------------- K0: pack weights (kh-major K) bf16 hi/lo + bias ----------------
__global__ void pack_kernel(const float* __restrict__ conv_w,
                            const float* __restrict__ conv_b,
                            const float* __restrict__ cc_w,
                            const float* __restrict__ cc_b) {
    int i = blockIdx.x * blockDim.x + threadIdx.x;
    if (i < MPAD * KDIM) {
        int m = i / KDIM, kk = i - m * KDIM;     // kk = kh*512 + ci
        int kh = kk >> 9, ci = kk & 511;
        float v = 0.f;
        if (m < 512)      v = conv_w[m * KDIM + ci * 7 + kh];
        else if (m < 522) v = cc_w[(m - 512) * KDIM + ci * 7 + kh];
        __nv_bfloat16 hi = __float2bfloat16(v);
        __nv_bfloat16 lo = __float2bfloat16(v - __bfloat162float(hi));
        g_wh[i] = hi;
        g_wl[i] = lo;
    }
    if (i < MPAD) {
        float bv = 0.f;
        if (i < 512)      bv = conv_b[i];
        else if (i < 522) bv = cc_b[i - 512];
        g_bias[i] = bv;
    }
}

// ---------------- K0b: transpose x -> [b,h,w,c] bf16 hi/lo ----------------
// grid: x = ctile(16)*10 wtiles? -> x: wt*16+ct, y: b*16+h ; block 256
__global__ void xt_kernel(const float* __restrict__ x) {
    __shared__ float xs[32][33];
    const int ct = blockIdx.x & 15;        // channel tile (16)
    const int wt = blockIdx.x >> 4;        // w tile (10)
    const int b  = blockIdx.y >> 4;
    const int h  = blockIdx.y & 15;
    const int tid = threadIdx.x;
    const float* xb = x + (size_t)b * BSTR + h * W_;
#pragma unroll
    for (int it = 0; it < 4; it++) {
        int e = tid + 256 * it;
        int c = e >> 5, w = e & 31;
        int gw = wt * 32 + w;
        xs[c][w] = (gw < W_) ? xb[(size_t)(ct * 32 + c) * HWX + gw] : 0.f;
    }
    __syncthreads();
    const size_t rowb = ((size_t)(b * 16 + h)) * W_;
#pragma unroll
    for (int it = 0; it < 4; it++) {
        int e = tid + 256 * it;
        int w = e >> 5, c = e & 31;
        int gw = wt * 32 + w;
        if (gw < W_) {
            float v = xs[c][w];
            __nv_bfloat16 hi = __float2bfloat16(v);
            __nv_bfloat16 lo = __float2bfloat16(v - __bfloat162float(hi));
            size_t o = (rowb + gw) * C_ + ct * 32 + c;
            g_xhi[o] = hi;
            g_xlo[o] = lo;
        }
    }
}

// ---------------- K1: conv+cc GEMM via mma.sync bf16 3-term split ----------------
// M=channels(640 pad), N=positions(48000). CTA 128x128, K-chunk 32, double buffer.
__global__ void __launch_bounds__(256, 1) conv_mma(int dummy) {
    extern __shared__ char sm[];
    const uint32_t smb = smem_u32(sm);
    const int tid  = threadIdx.x;
    const int wid  = tid >> 5;
    const int lane = tid & 31;
    const int mBase = blockIdx.y * MT;
    const int nBase = blockIdx.x * NT;

    // ---- loader setup: row = tid&127, thi = tid>>7 ----
    const int row = tid & 127;
    const int thi = tid >> 7;
    const int n   = nBase + row;
    const int b2  = n / P_;
    const int rem = n - b2 * P_;
    const int ho  = rem / W_;
    const int w   = rem - ho * W_;
    const size_t bRowBase = ((size_t)(b2 * 16 + ho) * W_ + w) * C_;

    const __nv_bfloat16* aPtr[4];
    const __nv_bfloat16* bPtr[4];
    uint32_t sOffA[4], sOffB[4];
#pragma unroll
    for (int it = 0; it < 4; it++) {
        const int arr = it >> 1;
        const int c16 = ((it & 1) << 1) | thi;
        aPtr[it] = (arr ? g_wl : g_wh) + (size_t)(mBase + row) * KDIM + c16 * 8;
        bPtr[it] = (arr ? g_xlo : g_xhi) + bRowBase + c16 * 8;
        sOffA[it] = (uint32_t)(arr * TILE_B + row * ROWB + c16 * 16);
        sOffB[it] = (uint32_t)(2 * TILE_B + arr * TILE_B + row * ROWB + c16 * 16);
    }

    // ---- per-warp ldmatrix base addresses ----
    const int mw = wid >> 2;           // 0..1
    const int nw = wid & 3;            // 0..3
    const uint32_t aAddr = (uint32_t)((mw * 64 + (lane & 15)) * ROWB + ((lane >> 4) << 4));
    const uint32_t bAddr = (uint32_t)(2 * TILE_B +
                           (nw * 32 + (lane & 7) + ((lane >> 4) << 3)) * ROWB +
                           (((lane >> 3) & 1) << 4));

    float acc[4][4][4];
#pragma unroll
    for (int i = 0; i < 4; i++)
#pragma unroll
        for (int j = 0; j < 4; j++)
#pragma unroll
            for (int r = 0; r < 4; r++) acc[i][j][r] = 0.f;

    // ---- prologue: chunk 0 -> buf 0 ----
    {
        uint4 va[4], vb[4];
#pragma unroll
        for (int it = 0; it < 4; it++) {
            va[it] = *(const uint4*)(aPtr[it]);
            vb[it] = *(const uint4*)(bPtr[it]);
        }
#pragma unroll
        for (int it = 0; it < 4; it++) {
            *(uint4*)(sm + sOffA[it]) = va[it];
            *(uint4*)(sm + sOffB[it]) = vb[it];
        }
    }
    __syncthreads();

#pragma unroll 1
    for (int i = 0; i < NCHUNK; i++) {
        const int cur = i & 1;
        uint4 va[4], vb[4];
        const bool hasNext = (i + 1) < NCHUNK;
        if (hasNext) {
            const int k0  = (i + 1) << 5;
            const int kh  = k0 >> 9;
            const int ci0 = k0 & 511;
            const size_t bo = (size_t)kh * (W_ * C_) + ci0;
#pragma unroll
            for (int it = 0; it < 4; it++) {
                va[it] = *(const uint4*)(aPtr[it] + k0);
                vb[it] = *(const uint4*)(bPtr[it] + bo);
            }
        }
        // ---- compute on buffer cur ----
        {
            const uint32_t base = smb + (uint32_t)cur * BUF_B;
#pragma unroll
            for (int q = 0; q < 2; q++) {
                const uint32_t qo = q * 32;
                uint32_t ah[4][4], al[4][4], bh[4][2], bl[4][2];
#pragma unroll
                for (int f = 0; f < 4; f++)
                    ldsm4(ah[f], base + aAddr + f * 1280 + qo);
#pragma unroll
                for (int f = 0; f < 4; f++)
                    ldsm4(al[f], base + TILE_B + aAddr + f * 1280 + qo);
#pragma unroll
                for (int t = 0; t < 2; t++) {
                    uint32_t r[4];
                    ldsm4(r, base + bAddr + t * 1280 + qo);
                    bh[2 * t][0] = r[0]; bh[2 * t][1] = r[1];
                    bh[2 * t + 1][0] = r[2]; bh[2 * t + 1][1] = r[3];
                    ldsm4(r, base + TILE_B + bAddr + t * 1280 + qo);
                    bl[2 * t][0] = r[0]; bl[2 * t][1] = r[1];
                    bl[2 * t + 1][0] = r[2]; bl[2 * t + 1][1] = r[3];
                }
#pragma unroll
                for (int f = 0; f < 4; f++)
#pragma unroll
                    for (int j = 0; j < 4; j++) {
                        mma_bf16(acc[f][j], ah[f], bh[j]);
                        mma_bf16(acc[f][j], ah[f], bl[j]);
                        mma_bf16(acc[f][j], al[f], bh[j]);
                    }
            }
        }
        if (hasNext) {
            char* bb = sm + (cur ^ 1) * BUF_B;
#pragma unroll
            for (int it = 0; it < 4; it++) {
                *(uint4*)(bb + sOffA[it]) = va[it];
                *(uint4*)(bb + sOffB[it]) = vb[it];
            }
        }
        __syncthreads();
    }

    // ---- epilogue: bias + relu, coalesced float2 stores ----
    float bias_v[4][2];
#pragma unroll
    for (int f = 0; f < 4; f++)
#pragma unroll
        for (int h = 0; h < 2; h++) {
            int m = mBase + mw * 64 + f * 16 + (lane >> 2) + 8 * h;
            bias_v[f][h] = (m < MREAL) ? g_bias[m] : 0.f;
        }
#pragma unroll
    for (int j = 0; j < 4; j++) {
        const int nj  = nBase + nw * 32 + j * 8 + (lane & 3) * 2;
        const int bj  = nj / P_;
        const int rj  = nj - bj * P_;
        const size_t fb = (size_t)bj * FEAT_BSTR + rj;
        const size_t sb = (size_t)bj * SCOR_BSTR + rj;
#pragma unroll
        for (int f = 0; f < 4; f++)
#pragma unroll
            for (int h = 0; h < 2; h++) {
                const int m = mBase + mw * 64 + f * 16 + (lane >> 2) + 8 * h;
                if (m >= MREAL) continue;
                float v0 = acc[f][j][2 * h]     + bias_v[f][h];
                float v1 = acc[f][j][2 * h + 1] + bias_v[f][h];
                if (m < 512) {
                    float2 o = make_float2(fmaxf(v0, 0.f), fmaxf(v1, 0.f));
                    *(float2*)(g_feats + fb + (size_t)m * P_) = o;
                } else {
                    float2 o = make_float2(v0, v1);
                    *(float2*)(g_scores + sb + (size_t)(m - 512) * P_) = o;
                }
            }
    }
}

// ---------------- K2: softmax over 10 cluster channels ----------------
__global__ void softmax_kernel() {
    int q = blockIdx.x * 256 + threadIdx.x;
    if (q >= NDIM) return;
    int b = q / P_;
    int rem = q - b * P_;
    int base = b * SCOR_BSTR + rem;
    float s[KG_];
    float mx = -1e30f;
#pragma unroll
    for (int k = 0; k < KG_; k++) { s[k] = g_scores[base + k * P_]; mx = fmaxf(mx, s[k]); }
    float sum = 0.f;
#pragma unroll
    for (int k = 0; k < KG_; k++) { s[k] = expf(s[k] - mx); sum += s[k]; }
    float inv = 1.f / sum;
#pragma unroll
    for (int k = 0; k < KG_; k++) g_assign[base + k * P_] = s[k] * inv;
}

// ---------------- K2b: asum ----------------
__global__ void asum_kernel() {
    int b = blockIdx.x >> 3, k = blockIdx.x & 7;
    const float* a = g_assign + b * SCOR_BSTR + k * P_;
    float s = 0.f;
    for (int i = threadIdx.x; i < P_; i += 256) s += a[i];
    __shared__ float red[256];
    red[threadIdx.x] = s;
    __syncthreads();
    for (int st = 128; st > 0; st >>= 1) {
        if (threadIdx.x < st) red[threadIdx.x] += red[threadIdx.x + st];
        __syncthreads();
    }
    if (threadIdx.x == 0) g_asum[blockIdx.x] = red[0];
}

// ---------------- K3: agg[b][k][c] = sum_p assign[b][k][p]*feats[b][c][p] ----------------
__global__ void agg_kernel() {
    __shared__ float fs[64][65];
    __shared__ float as[8][64];
    const int b = blockIdx.y;
    const int c0 = blockIdx.x * 64;
    const int t = threadIdx.x;
    const int k = t >> 6;
    const int c = t & 63;
    const float* fb = g_feats + (size_t)b * FEAT_BSTR + (size_t)c0 * P_;
    const float* ab = g_assign + b * SCOR_BSTR;
    float acc0 = 0.f, acc1 = 0.f;
    for (int p0 = 0; p0 < P_; p0 += 64) {
        int pc = P_ - p0; if (pc > 64) pc = 64;
#pragma unroll
        for (int idx = t; idx < 4096; idx += 256) {
            int cc = idx >> 6, pp = idx & 63;
            fs[cc][pp] = (pp < pc) ? fb[cc * P_ + p0 + pp] : 0.f;
        }
#pragma unroll
        for (int idx = t; idx < 512; idx += 256) {
            int kk = idx >> 6, pp = idx & 63;
            as[kk][pp] = (pp < pc) ? ab[kk * P_ + p0 + pp] : 0.f;
        }
        __syncthreads();
#pragma unroll
        for (int p = 0; p < 64; p++) {
            float f = fs[c][p];
            acc0 = fmaf(as[k][p], f, acc0);
            acc1 = fmaf(as[k + 4][p], f, acc1);
        }
        __syncthreads();
    }
    g_agg[b * 4096 + k * 512 + c0 + c] = acc0;
    g_agg[b * 4096 + (k + 4) * 512 + c0 + c] = acc1;
}

// ---------------- K4: residual + L2 normalize ----------------
__global__ void vlad_kernel(const float* __restrict__ centroids) {
    const int b = blockIdx.x >> 3, k = blockIdx.x & 7;
    const int t = threadIdx.x;
    const float asum = g_asum[blockIdx.x];
    const float* aggp = g_agg + b * 4096 + k * 512;
    const float* cen = centroids + k * 512;
    float r0 = aggp[t] - asum * cen[t];
    float r1 = aggp[t + 256] - asum * cen[t + 256];
    __shared__ float red[256];
    red[t] = r0 * r0 + r1 * r1;
    __syncthreads();
    for (int st = 128; st > 0; st >>= 1) {
        if (t < st) red[t] += red[t + st];
        __syncthreads();
    }
    __shared__ float scale_s;
    if (t == 0) scale_s = 1.f / fmaxf(sqrtf(red[0]), 1e-12f);
    __syncthreads();
    float sc = scale_s;
    g_vlad[b * 4096 + k * 512 + t] = r0 * sc;
    g_vlad[b * 4096 + k * 512 + t + 256] = r1 * sc;
}

// ---------------- K5: emb = relu(vlad @ fc_w^T + fc_b) ----------------
__global__ void emb_kernel(const float* __restrict__ fc_w,
                           const float* __restrict__ fc_b,
                           float* __restrict__ out) {
    const int b = blockIdx.y, co = blockIdx.x;
    const float4* v = (const float4*)(g_vlad + b * 4096);
    const float4* wr = (const float4*)(fc_w + (size_t)co * 4096);
    float s = 0.f;
    for (int i = threadIdx.x; i < 1024; i += 128) {
        float4 a = v[i], w4 = wr[i];
        s += a.x * w4.x + a.y * w4.y + a.z * w4.z + a.w * w4.w;
    }
    __shared__ float red[128];
    red[threadIdx.x] = s;
    __syncthreads();
    for (int st = 64; st > 0; st >>= 1) {
        if (threadIdx.x < st) red[threadIdx.x] += red[threadIdx.x + st];
        __syncthreads();
    }
    if (threadIdx.x == 0)
        out[b * 512 + co] = fmaxf(red[0] + fc_b[co], 0.f);
}

// ---------------- K6: logit = emb @ logit_w^T ----------------
__global__ void logit_kernel(const float* __restrict__ emb,
                             const float* __restrict__ lw,
                             float* __restrict__ out) {
    const int b = blockIdx.y, o = blockIdx.x;
    const float4* e = (const float4*)(emb + b * 512);
    const float4* wr = (const float4*)(lw + (size_t)o * 512);
    float s = 0.f;
    for (int i = threadIdx.x; i < 128; i += 64) {
        float4 a = e[i], w4 = wr[i];
        s += a.x * w4.x + a.y * w4.y + a.z * w4.z + a.w * w4.w;
    }
    __shared__ float red[64];
    red[threadIdx.x] = s;
    __syncthreads();
    for (int st = 32; st > 0; st >>= 1) {
        if (threadIdx.x < st) red[threadIdx.x] += red[threadIdx.x + st];
        __syncthreads();
    }
    if (threadIdx.x == 0) out[b * OUT_ + o] = red[0];
}

// ---------------- launch ----------------
extern "C" void kernel_launch(void* const* d_in, const int* in_sizes, int n_in,
                              void* d_out, int out_size) {
    const float* x5        = (const float*)d_in[0];
    const float* conv_w    = (const float*)d_in[5];
    const float* conv_b    = (const float*)d_in[6];
    const float* cc_w      = (const float*)d_in[7];
    const float* cc_b      = (const float*)d_in[8];
    const float* centroids = (const float*)d_in[9];
    const float* fc_w      = (const float*)d_in[10];
    const float* fc_b      = (const float*)d_in[11];
    const float* logit_w   = (const float*)d_in[12];
    float* out = (float*)d_out;

    cudaFuncSetAttribute(conv_mma, cudaFuncAttributeMaxDynamicSharedMemorySize, SMEM_TOTAL);

    pack_kernel<<<(MPAD * KDIM + 255) / 256, 256>>>(conv_w, conv_b, cc_w, cc_b);
    xt_kernel<<<dim3(160, 256), 256>>>(x5);
    conv_mma<<<dim3(NDIM / NT, MPAD / MT), 256, SMEM_TOTAL>>>(0);
    softmax_kernel<<<(NDIM + 255) / 256, 256>>>();
    asum_kernel<<<B_ * KC_, 256>>>();
    agg_kernel<<<dim3(8, B_), 256>>>();
    vlad_kernel<<<B_ * KC_, 256>>>(centroids);
    emb_kernel<<<dim3(C_, B_), 128>>>(fc_w, fc_b, out);
    logit_kernel<<<dim3(OUT_, B_), 64>>>(out, logit_w, out + B_ * C_);
}

// round 4
// speedup vs baseline: 2.4581x; 1.4851x over previous
#include <cuda_runtime.h>
#include <cuda_fp16.h>
#include <cstdint>
#include <math.h>

// ---------------- problem constants ----------------
#define B_        16
#define C_        512
#define H_        16
#define W_        300
#define HO_       10
#define KG_       10
#define KC_       8
#define OUT_      5994
#define KDIM      3584        // C_ * 7
#define NDIM      48000       // B_ * HO_ * W_
#define MPAD      640
#define MREAL     522
#define HWX       4800        // H_*W_
#define BSTR      2457600     // C_*H_*W_
#define P_        3000        // HO_*W_
#define FEAT_BSTR 1536000     // C_*P_
#define SCOR_BSTR 30000       // KG_*P_
#define XT_ROWS   (B_*H_*W_)  // 76800

// main GEMM tiling (feats: 512 channels x 48000 positions)
#define MT        128
#define NT        128
#define NCHUNK    112         // KDIM / 32
#define ROWB      80          // padded smem row stride (32 fp16 = 64B + 16B pad)
#define TILE_B    10240       // 128 rows * 80B
#define BUF_B     30720       // WHI | WLO | X
#define SMEM_TOTAL (2*BUF_B)  // 61440

// score GEMM smem
#define S_ATILE   1280        // 16 rows * 80B
#define S_BUF     12800       // AHI 1280 | ALO 1280 | B 10240
#define S_SMEM    (2*S_BUF)   // 25600

// ---------------- device scratch ----------------
__device__ __half g_wh[MPAD * KDIM];
__device__ __half g_wl[MPAD * KDIM];
__device__ float g_bias[MPAD];
__device__ __half g_xh[XT_ROWS * C_];
__device__ float g_feats[B_ * C_ * HO_ * W_];
__device__ float g_scores[B_ * KG_ * HO_ * W_];
__device__ float g_assign[B_ * KG_ * HO_ * W_];
__device__ float g_asum[B_ * KC_];
__device__ float g_agg[B_ * KC_ * C_];
__device__ float g_vlad[B_ * KC_ * C_];

// ---------------- helpers ----------------
__device__ __forceinline__ uint32_t smem_u32(const void* p) {
    uint32_t a;
    asm("{ .reg .u64 t; cvta.to.shared.u64 t, %1; cvt.u32.u64 %0, t; }" : "=r"(a) : "l"(p));
    return a;
}
__device__ __forceinline__ void ldsm4(uint32_t* r, uint32_t addr) {
    asm volatile("ldmatrix.sync.aligned.m8n8.x4.shared.b16 {%0,%1,%2,%3}, [%4];"
                 : "=r"(r[0]), "=r"(r[1]), "=r"(r[2]), "=r"(r[3]) : "r"(addr));
}
__device__ __forceinline__ void mma_f16(float* c, const uint32_t* a, const uint32_t* b) {
    asm volatile(
        "mma.sync.aligned.m16n8k16.row.col.f32.f16.f16.f32 "
        "{%0,%1,%2,%3},{%4,%5,%6,%7},{%8,%9},{%0,%1,%2,%3};"
        : "+f"(c[0]), "+f"(c[1]), "+f"(c[2]), "+f"(c[3])
        : "r"(a[0]), "r"(a[1]), "r"(a[2]), "r"(a[3]), "r"(b[0]), "r"(b[1]));
}

// ---------------- K0: pack weights (kh-major K) fp16 hi/lo + bias ----------------
__global__ void pack_kernel(const float* __restrict__ conv_w,
                            const float* __restrict__ conv_b,
                            const float* __restrict__ cc_w,
                            const float* __restrict__ cc_b) {
    int i = blockIdx.x * blockDim.x + threadIdx.x;
    if (i < MPAD * KDIM) {
        int m = i / KDIM, kk = i - m * KDIM;     // kk = kh*512 + ci
        int kh = kk >> 9, ci = kk & 511;
        float v = 0.f;
        if (m < 512)      v = conv_w[m * KDIM + ci * 7 + kh];
        else if (m < 522) v = cc_w[(m - 512) * KDIM + ci * 7 + kh];
        __half hi = __float2half_rn(v);
        __half lo = __float2half_rn(v - __half2float(hi));
        g_wh[i] = hi;
        g_wl[i] = lo;
    }
    if (i < MPAD) {
        float bv = 0.f;
        if (i < 512)      bv = conv_b[i];
        else if (i < 522) bv = cc_b[i - 512];
        g_bias[i] = bv;
    }
}

// ---------------- K0b: transpose x -> [b,h,w,c] fp16 ----------------
__global__ void xt_kernel(const float* __restrict__ x) {
    __shared__ float xs[32][33];
    const int ct = blockIdx.x & 15;        // channel tile (16)
    const int wt = blockIdx.x >> 4;        // w tile (10)
    const int b  = blockIdx.y >> 4;
    const int h  = blockIdx.y & 15;
    const int tid = threadIdx.x;
    const float* xb = x + (size_t)b * BSTR + h * W_;
#pragma unroll
    for (int it = 0; it < 4; it++) {
        int e = tid + 256 * it;
        int c = e >> 5, w = e & 31;
        int gw = wt * 32 + w;
        xs[c][w] = (gw < W_) ? xb[(size_t)(ct * 32 + c) * HWX + gw] : 0.f;
    }
    __syncthreads();
    const size_t rowb = ((size_t)(b * 16 + h)) * W_;
#pragma unroll
    for (int it = 0; it < 4; it++) {
        int e = tid + 256 * it;
        int w = e >> 5, c = e & 31;
        int gw = wt * 32 + w;
        if (gw < W_)
            g_xh[(rowb + gw) * C_ + ct * 32 + c] = __float2half_rn(xs[c][w]);
    }
}

// ---------------- K1: feats GEMM (512ch) via mma.sync fp16 2-term split ----------------
__global__ void __launch_bounds__(256, 1) conv_mma() {
    extern __shared__ char sm[];
    const uint32_t smb = smem_u32(sm);
    const int tid  = threadIdx.x;
    const int wid  = tid >> 5;
    const int lane = tid & 31;
    const int mBase = blockIdx.y * MT;
    const int nBase = blockIdx.x * NT;

    // ---- loader setup: row = tid&127, thi = tid>>7 ----
    const int row = tid & 127;
    const int thi = tid >> 7;
    const int n   = nBase + row;
    const int b2  = n / P_;
    const int rem = n - b2 * P_;
    const int ho  = rem / W_;
    const int w   = rem - ho * W_;
    const size_t bRowBase = ((size_t)(b2 * 16 + ho) * W_ + w) * C_;

    // 6 transfers/thread/chunk: WHI x2, WLO x2, X x2
    const __half* ptrs[6];
    uint32_t soff[6];
#pragma unroll
    for (int it = 0; it < 6; it++) {
        const int sel = it >> 1;                    // 0 WHI, 1 WLO, 2 X
        const int c16 = ((it & 1) << 1) | thi;      // 16B chunk 0..3
        if (sel == 0) {
            ptrs[it] = g_wh + (size_t)(mBase + row) * KDIM + c16 * 8;
            soff[it] = (uint32_t)(row * ROWB + c16 * 16);
        } else if (sel == 1) {
            ptrs[it] = g_wl + (size_t)(mBase + row) * KDIM + c16 * 8;
            soff[it] = (uint32_t)(TILE_B + row * ROWB + c16 * 16);
        } else {
            ptrs[it] = g_xh + bRowBase + c16 * 8;
            soff[it] = (uint32_t)(2 * TILE_B + row * ROWB + c16 * 16);
        }
    }

    // ---- per-warp ldmatrix base addresses ----
    const int mw = wid >> 2;           // 0..1
    const int nw = wid & 3;            // 0..3
    const uint32_t aAddr = (uint32_t)((mw * 64 + (lane & 15)) * ROWB + ((lane >> 4) << 4));
    const uint32_t bAddr = (uint32_t)(2 * TILE_B +
                           (nw * 32 + (lane & 7) + ((lane >> 4) << 3)) * ROWB +
                           (((lane >> 3) & 1) << 4));

    float acc[4][4][4];
#pragma unroll
    for (int i = 0; i < 4; i++)
#pragma unroll
        for (int j = 0; j < 4; j++)
#pragma unroll
            for (int r = 0; r < 4; r++) acc[i][j][r] = 0.f;

    // ---- prologue: chunk 0 -> buf 0 ----
    {
        uint4 v[6];
#pragma unroll
        for (int it = 0; it < 6; it++) v[it] = *(const uint4*)(ptrs[it]);
#pragma unroll
        for (int it = 0; it < 6; it++) *(uint4*)(sm + soff[it]) = v[it];
    }
    __syncthreads();

#pragma unroll 1
    for (int i = 0; i < NCHUNK; i++) {
        const int cur = i & 1;
        uint4 v[6];
        const bool hasNext = (i + 1) < NCHUNK;
        if (hasNext) {
            const int k0  = (i + 1) << 5;
            const int kh  = k0 >> 9;
            const int ci0 = k0 & 511;
            const size_t bo = (size_t)kh * (W_ * C_) + ci0;
#pragma unroll
            for (int it = 0; it < 6; it++)
                v[it] = *(const uint4*)(ptrs[it] + ((it < 4) ? (size_t)k0 : bo));
        }
        // ---- compute on buffer cur ----
        {
            const uint32_t base = smb + (uint32_t)cur * BUF_B;
#pragma unroll
            for (int q = 0; q < 2; q++) {
                const uint32_t qo = q * 32;
                uint32_t ah[4][4], al[4][4], bf[4][2];
#pragma unroll
                for (int f = 0; f < 4; f++)
                    ldsm4(ah[f], base + aAddr + f * 1280 + qo);
#pragma unroll
                for (int f = 0; f < 4; f++)
                    ldsm4(al[f], base + TILE_B + aAddr + f * 1280 + qo);
#pragma unroll
                for (int t = 0; t < 2; t++) {
                    uint32_t r[4];
                    ldsm4(r, base + bAddr + t * 1280 + qo);
                    bf[2 * t][0] = r[0]; bf[2 * t][1] = r[1];
                    bf[2 * t + 1][0] = r[2]; bf[2 * t + 1][1] = r[3];
                }
#pragma unroll
                for (int f = 0; f < 4; f++)
#pragma unroll
                    for (int j = 0; j < 4; j++) {
                        mma_f16(acc[f][j], ah[f], bf[j]);
                        mma_f16(acc[f][j], al[f], bf[j]);
                    }
            }
        }
        if (hasNext) {
            char* bb = sm + (cur ^ 1) * BUF_B;
#pragma unroll
            for (int it = 0; it < 6; it++) *(uint4*)(bb + soff[it]) = v[it];
        }
        __syncthreads();
    }

    // ---- epilogue: bias + relu, coalesced float2 stores (all m < 512) ----
    float bias_v[4][2];
#pragma unroll
    for (int f = 0; f < 4; f++)
#pragma unroll
        for (int h = 0; h < 2; h++)
            bias_v[f][h] = g_bias[mBase + mw * 64 + f * 16 + (lane >> 2) + 8 * h];
#pragma unroll
    for (int j = 0; j < 4; j++) {
        const int nj  = nBase + nw * 32 + j * 8 + (lane & 3) * 2;
        const int bj  = nj / P_;
        const int rj  = nj - bj * P_;
        const size_t fb = (size_t)bj * FEAT_BSTR + rj;
#pragma unroll
        for (int f = 0; f < 4; f++)
#pragma unroll
            for (int h = 0; h < 2; h++) {
                const int m = mBase + mw * 64 + f * 16 + (lane >> 2) + 8 * h;
                float2 o = make_float2(fmaxf(acc[f][j][2 * h]     + bias_v[f][h], 0.f),
                                       fmaxf(acc[f][j][2 * h + 1] + bias_v[f][h], 0.f));
                *(float2*)(g_feats + fb + (size_t)m * P_) = o;
            }
    }
}

// ---------------- K1b: scores GEMM (10ch via m16 tile) ----------------
__global__ void __launch_bounds__(128) score_mma() {
    extern __shared__ char sm[];
    const uint32_t smb = smem_u32(sm);
    const int tid  = threadIdx.x;
    const int wid  = tid >> 5;      // 0..3 = n-warp
    const int lane = tid & 31;
    const int nBase = blockIdx.x * NT;

    // B loader: row = tid, 4 chunks
    const int n   = nBase + tid;
    const int b2  = n / P_;
    const int rem = n - b2 * P_;
    const int ho  = rem / W_;
    const int w   = rem - ho * W_;
    const size_t bRowBase = ((size_t)(b2 * 16 + ho) * W_ + w) * C_;
    // A loader: 1 chunk/thread: 128 = 2 arrays * 16 rows * 4 chunks
    const int arr  = tid >> 6;
    const int arem = tid & 63;
    const int arow = arem >> 2;
    const int ac16 = arem & 3;
    const __half* aPtr = (arr ? g_wl : g_wh) + (size_t)(512 + arow) * KDIM + ac16 * 8;
    const uint32_t aSoff = (uint32_t)(arr * S_ATILE + arow * ROWB + ac16 * 16);

    const uint32_t aAddr = (uint32_t)((lane & 15) * ROWB + ((lane >> 4) << 4));
    const uint32_t bAddr = (uint32_t)(2 * S_ATILE +
                           (wid * 32 + (lane & 7) + ((lane >> 4) << 3)) * ROWB +
                           (((lane >> 3) & 1) << 4));

    float acc[4][4];
#pragma unroll
    for (int j = 0; j < 4; j++)
#pragma unroll
        for (int r = 0; r < 4; r++) acc[j][r] = 0.f;

    // prologue
    {
        uint4 va = *(const uint4*)aPtr;
        uint4 vb[4];
#pragma unroll
        for (int c = 0; c < 4; c++) vb[c] = *(const uint4*)(g_xh + bRowBase + c * 8);
        *(uint4*)(sm + aSoff) = va;
#pragma unroll
        for (int c = 0; c < 4; c++)
            *(uint4*)(sm + 2 * S_ATILE + tid * ROWB + c * 16) = vb[c];
    }
    __syncthreads();

#pragma unroll 1
    for (int i = 0; i < NCHUNK; i++) {
        const int cur = i & 1;
        uint4 va, vb[4];
        const bool hasNext = (i + 1) < NCHUNK;
        if (hasNext) {
            const int k0  = (i + 1) << 5;
            const int kh  = k0 >> 9;
            const int ci0 = k0 & 511;
            const size_t bo = (size_t)kh * (W_ * C_) + ci0;
            va = *(const uint4*)(aPtr + k0);
#pragma unroll
            for (int c = 0; c < 4; c++) vb[c] = *(const uint4*)(g_xh + bRowBase + bo + c * 8);
        }
        {
            const uint32_t base = smb + (uint32_t)cur * S_BUF;
#pragma unroll
            for (int q = 0; q < 2; q++) {
                const uint32_t qo = q * 32;
                uint32_t ah[4], al[4], bf[4][2];
                ldsm4(ah, base + aAddr + qo);
                ldsm4(al, base + S_ATILE + aAddr + qo);
#pragma unroll
                for (int t = 0; t < 2; t++) {
                    uint32_t r[4];
                    ldsm4(r, base + bAddr + t * 1280 + qo);
                    bf[2 * t][0] = r[0]; bf[2 * t][1] = r[1];
                    bf[2 * t + 1][0] = r[2]; bf[2 * t + 1][1] = r[3];
                }
#pragma unroll
                for (int j = 0; j < 4; j++) {
                    mma_f16(acc[j], ah, bf[j]);
                    mma_f16(acc[j], al, bf[j]);
                }
            }
        }
        if (hasNext) {
            char* bb = sm + (cur ^ 1) * S_BUF;
            *(uint4*)(bb + aSoff) = va;
#pragma unroll
            for (int c = 0; c < 4; c++)
                *(uint4*)(bb + 2 * S_ATILE + tid * ROWB + c * 16) = vb[c];
        }
        __syncthreads();
    }

    // epilogue: rows 0..9 real -> scores
#pragma unroll
    for (int j = 0; j < 4; j++) {
        const int nj  = nBase + wid * 32 + j * 8 + (lane & 3) * 2;
        const int bj  = nj / P_;
        const int rj  = nj - bj * P_;
        const size_t sb = (size_t)bj * SCOR_BSTR + rj;
#pragma unroll
        for (int h = 0; h < 2; h++) {
            const int m = (lane >> 2) + 8 * h;
            if (m < KG_) {
                float bv = g_bias[512 + m];
                float2 o = make_float2(acc[j][2 * h] + bv, acc[j][2 * h + 1] + bv);
                *(float2*)(g_scores + sb + (size_t)m * P_) = o;
            }
        }
    }
}

// ---------------- K2: softmax over 10 cluster channels ----------------
__global__ void softmax_kernel() {
    int q = blockIdx.x * 256 + threadIdx.x;
    if (q >= NDIM) return;
    int b = q / P_;
    int rem = q - b * P_;
    int base = b * SCOR_BSTR + rem;
    float s[KG_];
    float mx = -1e30f;
#pragma unroll
    for (int k = 0; k < KG_; k++) { s[k] = g_scores[base + k * P_]; mx = fmaxf(mx, s[k]); }
    float sum = 0.f;
#pragma unroll
    for (int k = 0; k < KG_; k++) { s[k] = expf(s[k] - mx); sum += s[k]; }
    float inv = 1.f / sum;
#pragma unroll
    for (int k = 0; k < KG_; k++) g_assign[base + k * P_] = s[k] * inv;
}

// ---------------- K2b: asum ----------------
__global__ void asum_kernel() {
    int b = blockIdx.x >> 3, k = blockIdx.x & 7;
    const float* a = g_assign + b * SCOR_BSTR + k * P_;
    float s = 0.f;
    for (int i = threadIdx.x; i < P_; i += 256) s += a[i];
    __shared__ float red[256];
    red[threadIdx.x] = s;
    __syncthreads();
    for (int st = 128; st > 0; st >>= 1) {
        if (threadIdx.x < st) red[threadIdx.x] += red[threadIdx.x + st];
        __syncthreads();
    }
    if (threadIdx.x == 0) g_asum[blockIdx.x] = red[0];
}

// ---------------- K3: agg[b][k][c] = sum_p assign[b][k][p]*feats[b][c][p] ----------------
__global__ void agg_kernel() {
    __shared__ float fs[64][65];
    __shared__ float as[8][64];
    const int b = blockIdx.y;
    const int c0 = blockIdx.x * 64;
    const int t = threadIdx.x;
    const int k = t >> 6;
    const int c = t & 63;
    const float* fb = g_feats + (size_t)b * FEAT_BSTR + (size_t)c0 * P_;
    const float* ab = g_assign + b * SCOR_BSTR;
    float acc0 = 0.f, acc1 = 0.f;
    for (int p0 = 0; p0 < P_; p0 += 64) {
        int pc = P_ - p0; if (pc > 64) pc = 64;
#pragma unroll
        for (int idx = t; idx < 4096; idx += 256) {
            int cc = idx >> 6, pp = idx & 63;
            fs[cc][pp] = (pp < pc) ? fb[cc * P_ + p0 + pp] : 0.f;
        }
#pragma unroll
        for (int idx = t; idx < 512; idx += 256) {
            int kk = idx >> 6, pp = idx & 63;
            as[kk][pp] = (pp < pc) ? ab[kk * P_ + p0 + pp] : 0.f;
        }
        __syncthreads();
#pragma unroll
        for (int p = 0; p < 64; p++) {
            float f = fs[c][p];
            acc0 = fmaf(as[k][p], f, acc0);
            acc1 = fmaf(as[k + 4][p], f, acc1);
        }
        __syncthreads();
    }
    g_agg[b * 4096 + k * 512 + c0 + c] = acc0;
    g_agg[b * 4096 + (k + 4) * 512 + c0 + c] = acc1;
}

// ---------------- K4: residual + L2 normalize ----------------
__global__ void vlad_kernel(const float* __restrict__ centroids) {
    const int b = blockIdx.x >> 3, k = blockIdx.x & 7;
    const int t = threadIdx.x;
    const float asum = g_asum[blockIdx.x];
    const float* aggp = g_agg + b * 4096 + k * 512;
    const float* cen = centroids + k * 512;
    float r0 = aggp[t] - asum * cen[t];
    float r1 = aggp[t + 256] - asum * cen[t + 256];
    __shared__ float red[256];
    red[t] = r0 * r0 + r1 * r1;
    __syncthreads();
    for (int st = 128; st > 0; st >>= 1) {
        if (t < st) red[t] += red[t + st];
        __syncthreads();
    }
    __shared__ float scale_s;
    if (t == 0) scale_s = 1.f / fmaxf(sqrtf(red[0]), 1e-12f);
    __syncthreads();
    float sc = scale_s;
    g_vlad[b * 4096 + k * 512 + t] = r0 * sc;
    g_vlad[b * 4096 + k * 512 + t + 256] = r1 * sc;
}

// ---------------- K5: emb = relu(vlad @ fc_w^T + fc_b) ----------------
__global__ void emb_kernel(const float* __restrict__ fc_w,
                           const float* __restrict__ fc_b,
                           float* __restrict__ out) {
    const int b = blockIdx.y, co = blockIdx.x;
    const float4* v = (const float4*)(g_vlad + b * 4096);
    const float4* wr = (const float4*)(fc_w + (size_t)co * 4096);
    float s = 0.f;
    for (int i = threadIdx.x; i < 1024; i += 128) {
        float4 a = v[i], w4 = wr[i];
        s += a.x * w4.x + a.y * w4.y + a.z * w4.z + a.w * w4.w;
    }
    __shared__ float red[128];
    red[threadIdx.x] = s;
    __syncthreads();
    for (int st = 64; st > 0; st >>= 1) {
        if (threadIdx.x < st) red[threadIdx.x] += red[threadIdx.x + st];
        __syncthreads();
    }
    if (threadIdx.x == 0)
        out[b * 512 + co] = fmaxf(red[0] + fc_b[co], 0.f);
}

// ---------------- K6: logit = emb @ logit_w^T ----------------
__global__ void logit_kernel(const float* __restrict__ emb,
                             const float* __restrict__ lw,
                             float* __restrict__ out) {
    const int b = blockIdx.y, o = blockIdx.x;
    const float4* e = (const float4*)(emb + b * 512);
    const float4* wr = (const float4*)(lw + (size_t)o * 512);
    float s = 0.f;
    for (int i = threadIdx.x; i < 128; i += 64) {
        float4 a = e[i], w4 = wr[i];
        s += a.x * w4.x + a.y * w4.y + a.z * w4.z + a.w * w4.w;
    }
    __shared__ float red[64];
    red[threadIdx.x] = s;
    __syncthreads();
    for (int st = 32; st > 0; st >>= 1) {
        if (threadIdx.x < st) red[threadIdx.x] += red[threadIdx.x + st];
        __syncthreads();
    }
    if (threadIdx.x == 0) out[b * OUT_ + o] = red[0];
}

// ---------------- launch ----------------
extern "C" void kernel_launch(void* const* d_in, const int* in_sizes, int n_in,
                              void* d_out, int out_size) {
    const float* x5        = (const float*)d_in[0];
    const float* conv_w    = (const float*)d_in[5];
    const float* conv_b    = (const float*)d_in[6];
    const float* cc_w      = (const float*)d_in[7];
    const float* cc_b      = (const float*)d_in[8];
    const float* centroids = (const float*)d_in[9];
    const float* fc_w      = (const float*)d_in[10];
    const float* fc_b      = (const float*)d_in[11];
    const float* logit_w   = (const float*)d_in[12];
    float* out = (float*)d_out;

    cudaFuncSetAttribute(conv_mma, cudaFuncAttributeMaxDynamicSharedMemorySize, SMEM_TOTAL);

    pack_kernel<<<(MPAD * KDIM + 255) / 256, 256>>>(conv_w, conv_b, cc_w, cc_b);
    xt_kernel<<<dim3(160, 256), 256>>>(x5);
    conv_mma<<<dim3(NDIM / NT, 4), 256, SMEM_TOTAL>>>();
    score_mma<<<NDIM / NT, 128, S_SMEM>>>();
    softmax_kernel<<<(NDIM + 255) / 256, 256>>>();
    asum_kernel<<<B_ * KC_, 256>>>();
    agg_kernel<<<dim3(8, B_), 256>>>();
    vlad_kernel<<<B_ * KC_, 256>>>(centroids);
    emb_kernel<<<dim3(C_, B_), 128>>>(fc_w, fc_b, out);
    logit_kernel<<<dim3(OUT_, B_), 64>>>(out, logit_w, out + B_ * C_);
}

// round 5
// speedup vs baseline: 3.6374x; 1.4797x over previous
#include <cuda_runtime.h>
#include <cuda_fp16.h>
#include <cstdint>
#include <math.h>

// ---------------- problem constants ----------------
#define B_        16
#define C_        512
#define H_        16
#define W_        300
#define HO_       10
#define KG_       10
#define KC_       8
#define OUT_      5994
#define KDIM      3584        // C_ * 7
#define NDIM      48000       // B_ * HO_ * W_
#define MPAD      640
#define MREAL     522
#define HWX       4800        // H_*W_
#define BSTR      2457600     // C_*H_*W_
#define P_        3000        // HO_*W_
#define FEAT_BSTR 1536000     // C_*P_
#define SCOR_BSTR 30000       // KG_*P_
#define XT_ROWS   (B_*H_*W_)  // 76800

// main GEMM tiling (feats: 512 channels x 48000 positions)
#define MT        128
#define NT        128
#define NCHUNK    112         // KDIM / 32
#define ROWB      80          // padded smem row stride (32 fp16 = 64B + 16B pad)
#define TILE_B    10240       // 128 rows * 80B
#define BUF_B     20480       // WH | X
#define SMEM_TOTAL (2*BUF_B)  // 40960

// score GEMM smem
#define S_ATILE   1280        // 16 rows * 80B
#define S_BUF     11520       // A 1280 | B 10240
#define S_SMEM    (2*S_BUF)   // 23040

// ---------------- device scratch ----------------
__device__ __half g_wh[MPAD * KDIM];
__device__ float g_bias[MPAD];
__device__ __half g_xh[XT_ROWS * C_];
__device__ float g_feats[B_ * C_ * HO_ * W_];
__device__ float g_scores[B_ * KG_ * HO_ * W_];
__device__ float g_assign[B_ * KG_ * HO_ * W_];
__device__ float g_asum[B_ * KC_];
__device__ float g_agg[B_ * KC_ * C_];
__device__ float g_vlad[B_ * KC_ * C_];

// ---------------- helpers ----------------
__device__ __forceinline__ uint32_t smem_u32(const void* p) {
    uint32_t a;
    asm("{ .reg .u64 t; cvta.to.shared.u64 t, %1; cvt.u32.u64 %0, t; }" : "=r"(a) : "l"(p));
    return a;
}
__device__ __forceinline__ void ldsm4(uint32_t* r, uint32_t addr) {
    asm volatile("ldmatrix.sync.aligned.m8n8.x4.shared.b16 {%0,%1,%2,%3}, [%4];"
                 : "=r"(r[0]), "=r"(r[1]), "=r"(r[2]), "=r"(r[3]) : "r"(addr));
}
__device__ __forceinline__ void mma_f16(float* c, const uint32_t* a, const uint32_t* b) {
    asm volatile(
        "mma.sync.aligned.m16n8k16.row.col.f32.f16.f16.f32 "
        "{%0,%1,%2,%3},{%4,%5,%6,%7},{%8,%9},{%0,%1,%2,%3};"
        : "+f"(c[0]), "+f"(c[1]), "+f"(c[2]), "+f"(c[3])
        : "r"(a[0]), "r"(a[1]), "r"(a[2]), "r"(a[3]), "r"(b[0]), "r"(b[1]));
}

// ---------------- K0: pack weights (kh-major K) fp16 + bias ----------------
__global__ void pack_kernel(const float* __restrict__ conv_w,
                            const float* __restrict__ conv_b,
                            const float* __restrict__ cc_w,
                            const float* __restrict__ cc_b) {
    int i = blockIdx.x * blockDim.x + threadIdx.x;
    if (i < MPAD * KDIM) {
        int m = i / KDIM, kk = i - m * KDIM;     // kk = kh*512 + ci
        int kh = kk >> 9, ci = kk & 511;
        float v = 0.f;
        if (m < 512)      v = conv_w[m * KDIM + ci * 7 + kh];
        else if (m < 522) v = cc_w[(m - 512) * KDIM + ci * 7 + kh];
        g_wh[i] = __float2half_rn(v);
    }
    if (i < MPAD) {
        float bv = 0.f;
        if (i < 512)      bv = conv_b[i];
        else if (i < 522) bv = cc_b[i - 512];
        g_bias[i] = bv;
    }
}

// ---------------- K0b: transpose x -> [b,h,w,c] fp16 ----------------
__global__ void xt_kernel(const float* __restrict__ x) {
    __shared__ float xs[32][33];
    const int ct = blockIdx.x & 15;        // channel tile (16)
    const int wt = blockIdx.x >> 4;        // w tile (10)
    const int b  = blockIdx.y >> 4;
    const int h  = blockIdx.y & 15;
    const int tid = threadIdx.x;
    const float* xb = x + (size_t)b * BSTR + h * W_;
#pragma unroll
    for (int it = 0; it < 4; it++) {
        int e = tid + 256 * it;
        int c = e >> 5, w = e & 31;
        int gw = wt * 32 + w;
        xs[c][w] = (gw < W_) ? xb[(size_t)(ct * 32 + c) * HWX + gw] : 0.f;
    }
    __syncthreads();
    const size_t rowb = ((size_t)(b * 16 + h)) * W_;
#pragma unroll
    for (int it = 0; it < 4; it++) {
        int e = tid + 256 * it;
        int w = e >> 5, c = e & 31;
        int gw = wt * 32 + w;
        if (gw < W_)
            g_xh[(rowb + gw) * C_ + ct * 32 + c] = __float2half_rn(xs[c][w]);
    }
}

// ---------------- K1: feats GEMM (512ch) via mma.sync fp16 single-term ----------------
__global__ void __launch_bounds__(256, 2) conv_mma() {
    extern __shared__ char sm[];
    const uint32_t smb = smem_u32(sm);
    const int tid  = threadIdx.x;
    const int wid  = tid >> 5;
    const int lane = tid & 31;
    const int mBase = blockIdx.y * MT;
    const int nBase = blockIdx.x * NT;

    // ---- loader setup: row = tid&127, thi = tid>>7 ----
    const int row = tid & 127;
    const int thi = tid >> 7;
    const int n   = nBase + row;
    const int b2  = n / P_;
    const int rem = n - b2 * P_;
    const int ho  = rem / W_;
    const int w   = rem - ho * W_;
    const size_t bRowBase = ((size_t)(b2 * 16 + ho) * W_ + w) * C_;

    // 4 transfers/thread/chunk: WH x2, X x2
    const __half* ptrs[4];
    uint32_t soff[4];
#pragma unroll
    for (int it = 0; it < 4; it++) {
        const int sel = it >> 1;                    // 0 WH, 1 X
        const int c16 = ((it & 1) << 1) | thi;      // 16B chunk 0..3
        if (sel == 0) {
            ptrs[it] = g_wh + (size_t)(mBase + row) * KDIM + c16 * 8;
            soff[it] = (uint32_t)(row * ROWB + c16 * 16);
        } else {
            ptrs[it] = g_xh + bRowBase + c16 * 8;
            soff[it] = (uint32_t)(TILE_B + row * ROWB + c16 * 16);
        }
    }

    // ---- per-warp ldmatrix base addresses ----
    const int mw = wid >> 2;           // 0..1
    const int nw = wid & 3;            // 0..3
    const uint32_t aAddr = (uint32_t)((mw * 64 + (lane & 15)) * ROWB + ((lane >> 4) << 4));
    const uint32_t bAddr = (uint32_t)(TILE_B +
                           (nw * 32 + (lane & 7) + ((lane >> 4) << 3)) * ROWB +
                           (((lane >> 3) & 1) << 4));

    float acc[4][4][4];
#pragma unroll
    for (int i = 0; i < 4; i++)
#pragma unroll
        for (int j = 0; j < 4; j++)
#pragma unroll
            for (int r = 0; r < 4; r++) acc[i][j][r] = 0.f;

    // ---- prologue: chunk 0 -> buf 0 ----
    {
        uint4 v[4];
#pragma unroll
        for (int it = 0; it < 4; it++) v[it] = *(const uint4*)(ptrs[it]);
#pragma unroll
        for (int it = 0; it < 4; it++) *(uint4*)(sm + soff[it]) = v[it];
    }
    __syncthreads();

#pragma unroll 1
    for (int i = 0; i < NCHUNK; i++) {
        const int cur = i & 1;
        uint4 v[4];
        const bool hasNext = (i + 1) < NCHUNK;
        if (hasNext) {
            const int k0  = (i + 1) << 5;
            const int kh  = k0 >> 9;
            const int ci0 = k0 & 511;
            const size_t bo = (size_t)kh * (W_ * C_) + ci0;
#pragma unroll
            for (int it = 0; it < 4; it++)
                v[it] = *(const uint4*)(ptrs[it] + ((it < 2) ? (size_t)k0 : bo));
        }
        // ---- compute on buffer cur ----
        {
            const uint32_t base = smb + (uint32_t)cur * BUF_B;
#pragma unroll
            for (int q = 0; q < 2; q++) {
                const uint32_t qo = q * 32;
                uint32_t ah[4][4], bf[4][2];
#pragma unroll
                for (int f = 0; f < 4; f++)
                    ldsm4(ah[f], base + aAddr + f * 1280 + qo);
#pragma unroll
                for (int t = 0; t < 2; t++) {
                    uint32_t r[4];
                    ldsm4(r, base + bAddr + t * 1280 + qo);
                    bf[2 * t][0] = r[0]; bf[2 * t][1] = r[1];
                    bf[2 * t + 1][0] = r[2]; bf[2 * t + 1][1] = r[3];
                }
#pragma unroll
                for (int f = 0; f < 4; f++)
#pragma unroll
                    for (int j = 0; j < 4; j++)
                        mma_f16(acc[f][j], ah[f], bf[j]);
            }
        }
        if (hasNext) {
            char* bb = sm + (cur ^ 1) * BUF_B;
#pragma unroll
            for (int it = 0; it < 4; it++) *(uint4*)(bb + soff[it]) = v[it];
        }
        __syncthreads();
    }

    // ---- epilogue: bias + relu, coalesced float2 stores (all m < 512) ----
    float bias_v[4][2];
#pragma unroll
    for (int f = 0; f < 4; f++)
#pragma unroll
        for (int h = 0; h < 2; h++)
            bias_v[f][h] = g_bias[mBase + mw * 64 + f * 16 + (lane >> 2) + 8 * h];
#pragma unroll
    for (int j = 0; j < 4; j++) {
        const int nj  = nBase + nw * 32 + j * 8 + (lane & 3) * 2;
        const int bj  = nj / P_;
        const int rj  = nj - bj * P_;
        const size_t fb = (size_t)bj * FEAT_BSTR + rj;
#pragma unroll
        for (int f = 0; f < 4; f++)
#pragma unroll
            for (int h = 0; h < 2; h++) {
                const int m = mBase + mw * 64 + f * 16 + (lane >> 2) + 8 * h;
                float2 o = make_float2(fmaxf(acc[f][j][2 * h]     + bias_v[f][h], 0.f),
                                       fmaxf(acc[f][j][2 * h + 1] + bias_v[f][h], 0.f));
                *(float2*)(g_feats + fb + (size_t)m * P_) = o;
            }
    }
}

// ---------------- K1b: scores GEMM (10ch via m16 tile, single-term) ----------------
__global__ void __launch_bounds__(128) score_mma() {
    extern __shared__ char sm[];
    const uint32_t smb = smem_u32(sm);
    const int tid  = threadIdx.x;
    const int wid  = tid >> 5;      // 0..3 = n-warp
    const int lane = tid & 31;
    const int nBase = blockIdx.x * NT;

    // B loader: row = tid, 4 chunks
    const int n   = nBase + tid;
    const int b2  = n / P_;
    const int rem = n - b2 * P_;
    const int ho  = rem / W_;
    const int w   = rem - ho * W_;
    const size_t bRowBase = ((size_t)(b2 * 16 + ho) * W_ + w) * C_;
    // A loader: 64 transfers: 16 rows * 4 chunks (tid < 64)
    const int arow = (tid & 63) >> 2;
    const int ac16 = tid & 3;
    const bool aact = tid < 64;
    const __half* aPtr = g_wh + (size_t)(512 + arow) * KDIM + ac16 * 8;
    const uint32_t aSoff = (uint32_t)(arow * ROWB + ac16 * 16);

    const uint32_t aAddr = (uint32_t)((lane & 15) * ROWB + ((lane >> 4) << 4));
    const uint32_t bAddr = (uint32_t)(S_ATILE +
                           (wid * 32 + (lane & 7) + ((lane >> 4) << 3)) * ROWB +
                           (((lane >> 3) & 1) << 4));

    float acc[4][4];
#pragma unroll
    for (int j = 0; j < 4; j++)
#pragma unroll
        for (int r = 0; r < 4; r++) acc[j][r] = 0.f;

    // prologue
    {
        uint4 vb[4];
#pragma unroll
        for (int c = 0; c < 4; c++) vb[c] = *(const uint4*)(g_xh + bRowBase + c * 8);
        if (aact) *(uint4*)(sm + aSoff) = *(const uint4*)aPtr;
#pragma unroll
        for (int c = 0; c < 4; c++)
            *(uint4*)(sm + S_ATILE + tid * ROWB + c * 16) = vb[c];
    }
    __syncthreads();

#pragma unroll 1
    for (int i = 0; i < NCHUNK; i++) {
        const int cur = i & 1;
        uint4 va, vb[4];
        const bool hasNext = (i + 1) < NCHUNK;
        if (hasNext) {
            const int k0  = (i + 1) << 5;
            const int kh  = k0 >> 9;
            const int ci0 = k0 & 511;
            const size_t bo = (size_t)kh * (W_ * C_) + ci0;
            if (aact) va = *(const uint4*)(aPtr + k0);
#pragma unroll
            for (int c = 0; c < 4; c++) vb[c] = *(const uint4*)(g_xh + bRowBase + bo + c * 8);
        }
        {
            const uint32_t base = smb + (uint32_t)cur * S_BUF;
#pragma unroll
            for (int q = 0; q < 2; q++) {
                const uint32_t qo = q * 32;
                uint32_t ah[4], bf[4][2];
                ldsm4(ah, base + aAddr + qo);
#pragma unroll
                for (int t = 0; t < 2; t++) {
                    uint32_t r[4];
                    ldsm4(r, base + bAddr + t * 1280 + qo);
                    bf[2 * t][0] = r[0]; bf[2 * t][1] = r[1];
                    bf[2 * t + 1][0] = r[2]; bf[2 * t + 1][1] = r[3];
                }
#pragma unroll
                for (int j = 0; j < 4; j++)
                    mma_f16(acc[j], ah, bf[j]);
            }
        }
        if (hasNext) {
            char* bb = sm + (cur ^ 1) * S_BUF;
            if (aact) *(uint4*)(bb + aSoff) = va;
#pragma unroll
            for (int c = 0; c < 4; c++)
                *(uint4*)(bb + S_ATILE + tid * ROWB + c * 16) = vb[c];
        }
        __syncthreads();
    }

    // epilogue: rows 0..9 real -> scores
#pragma unroll
    for (int j = 0; j < 4; j++) {
        const int nj  = nBase + wid * 32 + j * 8 + (lane & 3) * 2;
        const int bj  = nj / P_;
        const int rj  = nj - bj * P_;
        const size_t sb = (size_t)bj * SCOR_BSTR + rj;
#pragma unroll
        for (int h = 0; h < 2; h++) {
            const int m = (lane >> 2) + 8 * h;
            if (m < KG_) {
                float bv = g_bias[512 + m];
                float2 o = make_float2(acc[j][2 * h] + bv, acc[j][2 * h + 1] + bv);
                *(float2*)(g_scores + sb + (size_t)m * P_) = o;
            }
        }
    }
}

// ---------------- K2: softmax over 10 cluster channels ----------------
__global__ void softmax_kernel() {
    int q = blockIdx.x * 256 + threadIdx.x;
    if (q >= NDIM) return;
    int b = q / P_;
    int rem = q - b * P_;
    int base = b * SCOR_BSTR + rem;
    float s[KG_];
    float mx = -1e30f;
#pragma unroll
    for (int k = 0; k < KG_; k++) { s[k] = g_scores[base + k * P_]; mx = fmaxf(mx, s[k]); }
    float sum = 0.f;
#pragma unroll
    for (int k = 0; k < KG_; k++) { s[k] = expf(s[k] - mx); sum += s[k]; }
    float inv = 1.f / sum;
#pragma unroll
    for (int k = 0; k < KG_; k++) g_assign[base + k * P_] = s[k] * inv;
}

// ---------------- K2b: asum ----------------
__global__ void asum_kernel() {
    int b = blockIdx.x >> 3, k = blockIdx.x & 7;
    const float* a = g_assign + b * SCOR_BSTR + k * P_;
    float s = 0.f;
    for (int i = threadIdx.x; i < P_; i += 256) s += a[i];
    __shared__ float red[256];
    red[threadIdx.x] = s;
    __syncthreads();
    for (int st = 128; st > 0; st >>= 1) {
        if (threadIdx.x < st) red[threadIdx.x] += red[threadIdx.x + st];
        __syncthreads();
    }
    if (threadIdx.x == 0) g_asum[blockIdx.x] = red[0];
}

// ---------------- K3: agg[b][k][c] = sum_p assign[b][k][p]*feats[b][c][p] ----------------
__global__ void agg_kernel() {
    __shared__ float fs[64][65];
    __shared__ float as[8][64];
    const int b = blockIdx.y;
    const int c0 = blockIdx.x * 64;
    const int t = threadIdx.x;
    const int k = t >> 6;
    const int c = t & 63;
    const float* fb = g_feats + (size_t)b * FEAT_BSTR + (size_t)c0 * P_;
    const float* ab = g_assign + b * SCOR_BSTR;
    float acc0 = 0.f, acc1 = 0.f;
    for (int p0 = 0; p0 < P_; p0 += 64) {
        int pc = P_ - p0; if (pc > 64) pc = 64;
#pragma unroll
        for (int idx = t; idx < 4096; idx += 256) {
            int cc = idx >> 6, pp = idx & 63;
            fs[cc][pp] = (pp < pc) ? fb[cc * P_ + p0 + pp] : 0.f;
        }
#pragma unroll
        for (int idx = t; idx < 512; idx += 256) {
            int kk = idx >> 6, pp = idx & 63;
            as[kk][pp] = (pp < pc) ? ab[kk * P_ + p0 + pp] : 0.f;
        }
        __syncthreads();
#pragma unroll
        for (int p = 0; p < 64; p++) {
            float f = fs[c][p];
            acc0 = fmaf(as[k][p], f, acc0);
            acc1 = fmaf(as[k + 4][p], f, acc1);
        }
        __syncthreads();
    }
    g_agg[b * 4096 + k * 512 + c0 + c] = acc0;
    g_agg[b * 4096 + (k + 4) * 512 + c0 + c] = acc1;
}

// ---------------- K4: residual + L2 normalize ----------------
__global__ void vlad_kernel(const float* __restrict__ centroids) {
    const int b = blockIdx.x >> 3, k = blockIdx.x & 7;
    const int t = threadIdx.x;
    const float asum = g_asum[blockIdx.x];
    const float* aggp = g_agg + b * 4096 + k * 512;
    const float* cen = centroids + k * 512;
    float r0 = aggp[t] - asum * cen[t];
    float r1 = aggp[t + 256] - asum * cen[t + 256];
    __shared__ float red[256];
    red[t] = r0 * r0 + r1 * r1;
    __syncthreads();
    for (int st = 128; st > 0; st >>= 1) {
        if (t < st) red[t] += red[t + st];
        __syncthreads();
    }
    __shared__ float scale_s;
    if (t == 0) scale_s = 1.f / fmaxf(sqrtf(red[0]), 1e-12f);
    __syncthreads();
    float sc = scale_s;
    g_vlad[b * 4096 + k * 512 + t] = r0 * sc;
    g_vlad[b * 4096 + k * 512 + t + 256] = r1 * sc;
}

// ---------------- K5: emb = relu(vlad @ fc_w^T + fc_b) ----------------
__global__ void emb_kernel(const float* __restrict__ fc_w,
                           const float* __restrict__ fc_b,
                           float* __restrict__ out) {
    const int b = blockIdx.y, co = blockIdx.x;
    const float4* v = (const float4*)(g_vlad + b * 4096);
    const float4* wr = (const float4*)(fc_w + (size_t)co * 4096);
    float s = 0.f;
    for (int i = threadIdx.x; i < 1024; i += 128) {
        float4 a = v[i], w4 = wr[i];
        s += a.x * w4.x + a.y * w4.y + a.z * w4.z + a.w * w4.w;
    }
    __shared__ float red[128];
    red[threadIdx.x] = s;
    __syncthreads();
    for (int st = 64; st > 0; st >>= 1) {
        if (threadIdx.x < st) red[threadIdx.x] += red[threadIdx.x + st];
        __syncthreads();
    }
    if (threadIdx.x == 0)
        out[b * 512 + co] = fmaxf(red[0] + fc_b[co], 0.f);
}

// ---------------- K6: logit = emb @ logit_w^T ----------------
__global__ void logit_kernel(const float* __restrict__ emb,
                             const float* __restrict__ lw,
                             float* __restrict__ out) {
    const int b = blockIdx.y, o = blockIdx.x;
    const float4* e = (const float4*)(emb + b * 512);
    const float4* wr = (const float4*)(lw + (size_t)o * 512);
    float s = 0.f;
    for (int i = threadIdx.x; i < 128; i += 64) {
        float4 a = e[i], w4 = wr[i];
        s += a.x * w4.x + a.y * w4.y + a.z * w4.z + a.w * w4.w;
    }
    __shared__ float red[64];
    red[threadIdx.x] = s;
    __syncthreads();
    for (int st = 32; st > 0; st >>= 1) {
        if (threadIdx.x < st) red[threadIdx.x] += red[threadIdx.x + st];
        __syncthreads();
    }
    if (threadIdx.x == 0) out[b * OUT_ + o] = red[0];
}

// ---------------- launch ----------------
extern "C" void kernel_launch(void* const* d_in, const int* in_sizes, int n_in,
                              void* d_out, int out_size) {
    const float* x5        = (const float*)d_in[0];
    const float* conv_w    = (const float*)d_in[5];
    const float* conv_b    = (const float*)d_in[6];
    const float* cc_w      = (const float*)d_in[7];
    const float* cc_b      = (const float*)d_in[8];
    const float* centroids = (const float*)d_in[9];
    const float* fc_w      = (const float*)d_in[10];
    const float* fc_b      = (const float*)d_in[11];
    const float* logit_w   = (const float*)d_in[12];
    float* out = (float*)d_out;

    cudaFuncSetAttribute(conv_mma, cudaFuncAttributeMaxDynamicSharedMemorySize, SMEM_TOTAL);

    pack_kernel<<<(MPAD * KDIM + 255) / 256, 256>>>(conv_w, conv_b, cc_w, cc_b);
    xt_kernel<<<dim3(160, 256), 256>>>(x5);
    conv_mma<<<dim3(NDIM / NT, 4), 256, SMEM_TOTAL>>>();
    score_mma<<<NDIM / NT, 128, S_SMEM>>>();
    softmax_kernel<<<(NDIM + 255) / 256, 256>>>();
    asum_kernel<<<B_ * KC_, 256>>>();
    agg_kernel<<<dim3(8, B_), 256>>>();
    vlad_kernel<<<B_ * KC_, 256>>>(centroids);
    emb_kernel<<<dim3(C_, B_), 128>>>(fc_w, fc_b, out);
    logit_kernel<<<dim3(OUT_, B_), 64>>>(out, logit_w, out + B_ * C_);
}

// round 6
// speedup vs baseline: 3.6887x; 1.0141x over previous
#include <cuda_runtime.h>
#include <cuda_fp16.h>
#include <cstdint>
#include <math.h>

// ---------------- problem constants ----------------
#define B_        16
#define C_        512
#define H_        16
#define W_        300
#define HO_       10
#define KG_       10
#define KC_       8
#define OUT_      5994
#define KDIM      3584        // C_ * 7
#define NDIM      48000       // B_ * HO_ * W_
#define MPAD      640
#define MREAL     522
#define HWX       4800        // H_*W_
#define BSTR      2457600     // C_*H_*W_
#define P_        3000        // HO_*W_
#define FEAT_BSTR 1536000     // C_*P_
#define SCOR_BSTR 30000       // KG_*P_
#define XT_ROWS   (B_*H_*W_)  // 76800

// main GEMM tiling (feats: 512 channels x 48000 positions)
#define MT        128
#define NT        128
#define NCHUNK    112         // KDIM / 32
#define ROWB      80          // padded smem row stride (32 fp16 = 64B + 16B pad)
#define TILE_B    10240       // 128 rows * 80B
#define BUF_B     20480       // WH | X
#define SMEM_TOTAL (2*BUF_B)  // 40960

// score GEMM: k-split
#define KSPLIT    4
#define SCHUNK    (NCHUNK / KSPLIT)   // 28
#define S_ATILE   1280        // 16 rows * 80B
#define S_BUF     11520       // A 1280 | B 10240
#define S_SMEM    (2*S_BUF)   // 23040

// ---------------- device scratch ----------------
__device__ __half g_wh[MPAD * KDIM];
__device__ float g_bias[MPAD];
__device__ __half g_xh[XT_ROWS * C_];
__device__ __half g_feats[B_ * C_ * HO_ * W_];
__device__ float g_scores[B_ * KG_ * HO_ * W_];
__device__ float g_assign[B_ * KG_ * HO_ * W_];
__device__ float g_asum[B_ * KC_];
__device__ float g_agg[B_ * KC_ * C_];
__device__ float g_vlad[B_ * KC_ * C_];

// ---------------- helpers ----------------
__device__ __forceinline__ uint32_t smem_u32(const void* p) {
    uint32_t a;
    asm("{ .reg .u64 t; cvta.to.shared.u64 t, %1; cvt.u32.u64 %0, t; }" : "=r"(a) : "l"(p));
    return a;
}
__device__ __forceinline__ void ldsm4(uint32_t* r, uint32_t addr) {
    asm volatile("ldmatrix.sync.aligned.m8n8.x4.shared.b16 {%0,%1,%2,%3}, [%4];"
                 : "=r"(r[0]), "=r"(r[1]), "=r"(r[2]), "=r"(r[3]) : "r"(addr));
}
__device__ __forceinline__ void mma_f16(float* c, const uint32_t* a, const uint32_t* b) {
    asm volatile(
        "mma.sync.aligned.m16n8k16.row.col.f32.f16.f16.f32 "
        "{%0,%1,%2,%3},{%4,%5,%6,%7},{%8,%9},{%0,%1,%2,%3};"
        : "+f"(c[0]), "+f"(c[1]), "+f"(c[2]), "+f"(c[3])
        : "r"(a[0]), "r"(a[1]), "r"(a[2]), "r"(a[3]), "r"(b[0]), "r"(b[1]));
}

// ---------------- K0: pack weights (kh-major K) fp16 + bias ----------------
__global__ void pack_kernel(const float* __restrict__ conv_w,
                            const float* __restrict__ conv_b,
                            const float* __restrict__ cc_w,
                            const float* __restrict__ cc_b) {
    int i = blockIdx.x * blockDim.x + threadIdx.x;
    if (i < MPAD * KDIM) {
        int m = i / KDIM, kk = i - m * KDIM;     // kk = kh*512 + ci
        int kh = kk >> 9, ci = kk & 511;
        float v = 0.f;
        if (m < 512)      v = conv_w[m * KDIM + ci * 7 + kh];
        else if (m < 522) v = cc_w[(m - 512) * KDIM + ci * 7 + kh];
        g_wh[i] = __float2half_rn(v);
    }
    if (i < MPAD) {
        float bv = 0.f;
        if (i < 512)      bv = conv_b[i];
        else if (i < 522) bv = cc_b[i - 512];
        g_bias[i] = bv;
    }
}

// ---------------- K0c: init scores with bias (atomic accumulation target) ----
__global__ void init_scores() {
    int i = blockIdx.x * 256 + threadIdx.x;
    if (i < B_ * SCOR_BSTR) {
        int k = (i % SCOR_BSTR) / P_;
        g_scores[i] = g_bias[512 + k];
    }
}

// ---------------- K0b: transpose x -> [b,h,w,c] fp16 ----------------
__global__ void xt_kernel(const float* __restrict__ x) {
    __shared__ float xs[32][33];
    const int ct = blockIdx.x & 15;        // channel tile (16)
    const int wt = blockIdx.x >> 4;        // w tile (10)
    const int b  = blockIdx.y >> 4;
    const int h  = blockIdx.y & 15;
    const int tid = threadIdx.x;
    const float* xb = x + (size_t)b * BSTR + h * W_;
#pragma unroll
    for (int it = 0; it < 4; it++) {
        int e = tid + 256 * it;
        int c = e >> 5, w = e & 31;
        int gw = wt * 32 + w;
        xs[c][w] = (gw < W_) ? xb[(size_t)(ct * 32 + c) * HWX + gw] : 0.f;
    }
    __syncthreads();
    const size_t rowb = ((size_t)(b * 16 + h)) * W_;
#pragma unroll
    for (int it = 0; it < 4; it++) {
        int e = tid + 256 * it;
        int w = e >> 5, c = e & 31;
        int gw = wt * 32 + w;
        if (gw < W_)
            g_xh[(rowb + gw) * C_ + ct * 32 + c] = __float2half_rn(xs[c][w]);
    }
}

// ---------------- K1: feats GEMM (512ch) via mma.sync fp16 ----------------
__global__ void __launch_bounds__(256, 2) conv_mma() {
    extern __shared__ char sm[];
    const uint32_t smb = smem_u32(sm);
    const int tid  = threadIdx.x;
    const int wid  = tid >> 5;
    const int lane = tid & 31;
    const int mBase = blockIdx.y * MT;
    const int nBase = blockIdx.x * NT;

    // ---- loader setup: row = tid&127, thi = tid>>7 ----
    const int row = tid & 127;
    const int thi = tid >> 7;
    const int n   = nBase + row;
    const int b2  = n / P_;
    const int rem = n - b2 * P_;
    const int ho  = rem / W_;
    const int w   = rem - ho * W_;
    const size_t bRowBase = ((size_t)(b2 * 16 + ho) * W_ + w) * C_;

    // 4 transfers/thread/chunk: WH x2, X x2
    const __half* ptrs[4];
    uint32_t soff[4];
#pragma unroll
    for (int it = 0; it < 4; it++) {
        const int sel = it >> 1;                    // 0 WH, 1 X
        const int c16 = ((it & 1) << 1) | thi;      // 16B chunk 0..3
        if (sel == 0) {
            ptrs[it] = g_wh + (size_t)(mBase + row) * KDIM + c16 * 8;
            soff[it] = (uint32_t)(row * ROWB + c16 * 16);
        } else {
            ptrs[it] = g_xh + bRowBase + c16 * 8;
            soff[it] = (uint32_t)(TILE_B + row * ROWB + c16 * 16);
        }
    }

    // ---- per-warp ldmatrix base addresses ----
    const int mw = wid >> 2;           // 0..1
    const int nw = wid & 3;            // 0..3
    const uint32_t aAddr = (uint32_t)((mw * 64 + (lane & 15)) * ROWB + ((lane >> 4) << 4));
    const uint32_t bAddr = (uint32_t)(TILE_B +
                           (nw * 32 + (lane & 7) + ((lane >> 4) << 3)) * ROWB +
                           (((lane >> 3) & 1) << 4));

    float acc[4][4][4];
#pragma unroll
    for (int i = 0; i < 4; i++)
#pragma unroll
        for (int j = 0; j < 4; j++)
#pragma unroll
            for (int r = 0; r < 4; r++) acc[i][j][r] = 0.f;

    // ---- prologue: chunk 0 -> buf 0 ----
    {
        uint4 v[4];
#pragma unroll
        for (int it = 0; it < 4; it++) v[it] = *(const uint4*)(ptrs[it]);
#pragma unroll
        for (int it = 0; it < 4; it++) *(uint4*)(sm + soff[it]) = v[it];
    }
    __syncthreads();

#pragma unroll 1
    for (int i = 0; i < NCHUNK; i++) {
        const int cur = i & 1;
        uint4 v[4];
        const bool hasNext = (i + 1) < NCHUNK;
        if (hasNext) {
            const int k0  = (i + 1) << 5;
            const int kh  = k0 >> 9;
            const int ci0 = k0 & 511;
            const size_t bo = (size_t)kh * (W_ * C_) + ci0;
#pragma unroll
            for (int it = 0; it < 4; it++)
                v[it] = *(const uint4*)(ptrs[it] + ((it < 2) ? (size_t)k0 : bo));
        }
        // ---- compute on buffer cur ----
        {
            const uint32_t base = smb + (uint32_t)cur * BUF_B;
#pragma unroll
            for (int q = 0; q < 2; q++) {
                const uint32_t qo = q * 32;
                uint32_t ah[4][4], bf[4][2];
#pragma unroll
                for (int f = 0; f < 4; f++)
                    ldsm4(ah[f], base + aAddr + f * 1280 + qo);
#pragma unroll
                for (int t = 0; t < 2; t++) {
                    uint32_t r[4];
                    ldsm4(r, base + bAddr + t * 1280 + qo);
                    bf[2 * t][0] = r[0]; bf[2 * t][1] = r[1];
                    bf[2 * t + 1][0] = r[2]; bf[2 * t + 1][1] = r[3];
                }
#pragma unroll
                for (int f = 0; f < 4; f++)
#pragma unroll
                    for (int j = 0; j < 4; j++)
                        mma_f16(acc[f][j], ah[f], bf[j]);
            }
        }
        if (hasNext) {
            char* bb = sm + (cur ^ 1) * BUF_B;
#pragma unroll
            for (int it = 0; it < 4; it++) *(uint4*)(bb + soff[it]) = v[it];
        }
        __syncthreads();
    }

    // ---- epilogue: bias + relu, fp16 stores (all m < 512) ----
    float bias_v[4][2];
#pragma unroll
    for (int f = 0; f < 4; f++)
#pragma unroll
        for (int h = 0; h < 2; h++)
            bias_v[f][h] = g_bias[mBase + mw * 64 + f * 16 + (lane >> 2) + 8 * h];
#pragma unroll
    for (int j = 0; j < 4; j++) {
        const int nj  = nBase + nw * 32 + j * 8 + (lane & 3) * 2;
        const int bj  = nj / P_;
        const int rj  = nj - bj * P_;
        const size_t fb = (size_t)bj * FEAT_BSTR + rj;
#pragma unroll
        for (int f = 0; f < 4; f++)
#pragma unroll
            for (int h = 0; h < 2; h++) {
                const int m = mBase + mw * 64 + f * 16 + (lane >> 2) + 8 * h;
                __half2 o = __floats2half2_rn(
                    fmaxf(acc[f][j][2 * h]     + bias_v[f][h], 0.f),
                    fmaxf(acc[f][j][2 * h + 1] + bias_v[f][h], 0.f));
                *(__half2*)(g_feats + fb + (size_t)m * P_) = o;
            }
    }
}

// ---------------- K1b: scores GEMM, k-split x4 with atomic merge ----------------
__global__ void __launch_bounds__(128) score_mma() {
    extern __shared__ char sm[];
    const uint32_t smb = smem_u32(sm);
    const int tid  = threadIdx.x;
    const int wid  = tid >> 5;      // 0..3 = n-warp
    const int lane = tid & 31;
    const int nBase = blockIdx.x * NT;
    const int cBase = blockIdx.y * SCHUNK;     // chunk segment

    // B loader: row = tid, 4 chunks
    const int n   = nBase + tid;
    const int b2  = n / P_;
    const int rem = n - b2 * P_;
    const int ho  = rem / W_;
    const int w   = rem - ho * W_;
    const size_t bRowBase = ((size_t)(b2 * 16 + ho) * W_ + w) * C_;
    // A loader: 64 transfers: 16 rows * 4 chunks (tid < 64)
    const int arow = (tid & 63) >> 2;
    const int ac16 = tid & 3;
    const bool aact = tid < 64;
    const __half* aPtr = g_wh + (size_t)(512 + arow) * KDIM + ac16 * 8;
    const uint32_t aSoff = (uint32_t)(arow * ROWB + ac16 * 16);

    const uint32_t aAddr = (uint32_t)((lane & 15) * ROWB + ((lane >> 4) << 4));
    const uint32_t bAddr = (uint32_t)(S_ATILE +
                           (wid * 32 + (lane & 7) + ((lane >> 4) << 3)) * ROWB +
                           (((lane >> 3) & 1) << 4));

    float acc[4][4];
#pragma unroll
    for (int j = 0; j < 4; j++)
#pragma unroll
        for (int r = 0; r < 4; r++) acc[j][r] = 0.f;

    // prologue: chunk cBase
    {
        const int k0  = cBase << 5;
        const int kh  = k0 >> 9;
        const int ci0 = k0 & 511;
        const size_t bo = (size_t)kh * (W_ * C_) + ci0;
        uint4 vb[4];
#pragma unroll
        for (int c = 0; c < 4; c++) vb[c] = *(const uint4*)(g_xh + bRowBase + bo + c * 8);
        if (aact) *(uint4*)(sm + aSoff) = *(const uint4*)(aPtr + k0);
#pragma unroll
        for (int c = 0; c < 4; c++)
            *(uint4*)(sm + S_ATILE + tid * ROWB + c * 16) = vb[c];
    }
    __syncthreads();

#pragma unroll 1
    for (int i = 0; i < SCHUNK; i++) {
        const int cur = i & 1;
        uint4 va, vb[4];
        const bool hasNext = (i + 1) < SCHUNK;
        if (hasNext) {
            const int k0  = (cBase + i + 1) << 5;
            const int kh  = k0 >> 9;
            const int ci0 = k0 & 511;
            const size_t bo = (size_t)kh * (W_ * C_) + ci0;
            if (aact) va = *(const uint4*)(aPtr + k0);
#pragma unroll
            for (int c = 0; c < 4; c++) vb[c] = *(const uint4*)(g_xh + bRowBase + bo + c * 8);
        }
        {
            const uint32_t base = smb + (uint32_t)cur * S_BUF;
#pragma unroll
            for (int q = 0; q < 2; q++) {
                const uint32_t qo = q * 32;
                uint32_t ah[4], bf[4][2];
                ldsm4(ah, base + aAddr + qo);
#pragma unroll
                for (int t = 0; t < 2; t++) {
                    uint32_t r[4];
                    ldsm4(r, base + bAddr + t * 1280 + qo);
                    bf[2 * t][0] = r[0]; bf[2 * t][1] = r[1];
                    bf[2 * t + 1][0] = r[2]; bf[2 * t + 1][1] = r[3];
                }
#pragma unroll
                for (int j = 0; j < 4; j++)
                    mma_f16(acc[j], ah, bf[j]);
            }
        }
        if (hasNext) {
            char* bb = sm + (cur ^ 1) * S_BUF;
            if (aact) *(uint4*)(bb + aSoff) = va;
#pragma unroll
            for (int c = 0; c < 4; c++)
                *(uint4*)(bb + S_ATILE + tid * ROWB + c * 16) = vb[c];
        }
        __syncthreads();
    }

    // epilogue: rows 0..9 real -> atomic merge into scores
#pragma unroll
    for (int j = 0; j < 4; j++) {
        const int nj  = nBase + wid * 32 + j * 8 + (lane & 3) * 2;
        const int bj  = nj / P_;
        const int rj  = nj - bj * P_;
        const size_t sb = (size_t)bj * SCOR_BSTR + rj;
#pragma unroll
        for (int h = 0; h < 2; h++) {
            const int m = (lane >> 2) + 8 * h;
            if (m < KG_) {
                atomicAdd(g_scores + sb + (size_t)m * P_,     acc[j][2 * h]);
                atomicAdd(g_scores + sb + (size_t)m * P_ + 1, acc[j][2 * h + 1]);
            }
        }
    }
}

// ---------------- K2: softmax over 10 cluster channels ----------------
__global__ void softmax_kernel() {
    int q = blockIdx.x * 256 + threadIdx.x;
    if (q >= NDIM) return;
    int b = q / P_;
    int rem = q - b * P_;
    int base = b * SCOR_BSTR + rem;
    float s[KG_];
    float mx = -1e30f;
#pragma unroll
    for (int k = 0; k < KG_; k++) { s[k] = g_scores[base + k * P_]; mx = fmaxf(mx, s[k]); }
    float sum = 0.f;
#pragma unroll
    for (int k = 0; k < KG_; k++) { s[k] = expf(s[k] - mx); sum += s[k]; }
    float inv = 1.f / sum;
#pragma unroll
    for (int k = 0; k < KG_; k++) g_assign[base + k * P_] = s[k] * inv;
}

// ---------------- K2b: asum ----------------
__global__ void asum_kernel() {
    int b = blockIdx.x >> 3, k = blockIdx.x & 7;
    const float* a = g_assign + b * SCOR_BSTR + k * P_;
    float s = 0.f;
    for (int i = threadIdx.x; i < P_; i += 256) s += a[i];
    __shared__ float red[256];
    red[threadIdx.x] = s;
    __syncthreads();
    for (int st = 128; st > 0; st >>= 1) {
        if (threadIdx.x < st) red[threadIdx.x] += red[threadIdx.x + st];
        __syncthreads();
    }
    if (threadIdx.x == 0) g_asum[blockIdx.x] = red[0];
}

// ---------------- K3: agg[b][k][c] = sum_p assign[b][k][p]*feats[b][c][p] ----------------
__global__ void agg_kernel() {
    __shared__ float fs[64][65];
    __shared__ float as[8][64];
    const int b = blockIdx.y;
    const int c0 = blockIdx.x * 64;
    const int t = threadIdx.x;
    const int k = t >> 6;
    const int c = t & 63;
    const __half* fb = g_feats + (size_t)b * FEAT_BSTR + (size_t)c0 * P_;
    const float* ab = g_assign + b * SCOR_BSTR;
    float acc0 = 0.f, acc1 = 0.f;
    for (int p0 = 0; p0 < P_; p0 += 64) {
        int pc = P_ - p0; if (pc > 64) pc = 64;
#pragma unroll
        for (int idx = t; idx < 4096; idx += 256) {
            int cc = idx >> 6, pp = idx & 63;
            fs[cc][pp] = (pp < pc) ? __half2float(fb[cc * P_ + p0 + pp]) : 0.f;
        }
#pragma unroll
        for (int idx = t; idx < 512; idx += 256) {
            int kk = idx >> 6, pp = idx & 63;
            as[kk][pp] = (pp < pc) ? ab[kk * P_ + p0 + pp] : 0.f;
        }
        __syncthreads();
#pragma unroll
        for (int p = 0; p < 64; p++) {
            float f = fs[c][p];
            acc0 = fmaf(as[k][p], f, acc0);
            acc1 = fmaf(as[k + 4][p], f, acc1);
        }
        __syncthreads();
    }
    g_agg[b * 4096 + k * 512 + c0 + c] = acc0;
    g_agg[b * 4096 + (k + 4) * 512 + c0 + c] = acc1;
}

// ---------------- K4: residual + L2 normalize ----------------
__global__ void vlad_kernel(const float* __restrict__ centroids) {
    const int b = blockIdx.x >> 3, k = blockIdx.x & 7;
    const int t = threadIdx.x;
    const float asum = g_asum[blockIdx.x];
    const float* aggp = g_agg + b * 4096 + k * 512;
    const float* cen = centroids + k * 512;
    float r0 = aggp[t] - asum * cen[t];
    float r1 = aggp[t + 256] - asum * cen[t + 256];
    __shared__ float red[256];
    red[t] = r0 * r0 + r1 * r1;
    __syncthreads();
    for (int st = 128; st > 0; st >>= 1) {
        if (t < st) red[t] += red[t + st];
        __syncthreads();
    }
    __shared__ float scale_s;
    if (t == 0) scale_s = 1.f / fmaxf(sqrtf(red[0]), 1e-12f);
    __syncthreads();
    float sc = scale_s;
    g_vlad[b * 4096 + k * 512 + t] = r0 * sc;
    g_vlad[b * 4096 + k * 512 + t + 256] = r1 * sc;
}

// ---------------- K5: emb = relu(vlad @ fc_w^T + fc_b) ----------------
__global__ void emb_kernel(const float* __restrict__ fc_w,
                           const float* __restrict__ fc_b,
                           float* __restrict__ out) {
    const int b = blockIdx.y, co = blockIdx.x;
    const float4* v = (const float4*)(g_vlad + b * 4096);
    const float4* wr = (const float4*)(fc_w + (size_t)co * 4096);
    float s = 0.f;
    for (int i = threadIdx.x; i < 1024; i += 128) {
        float4 a = v[i], w4 = wr[i];
        s += a.x * w4.x + a.y * w4.y + a.z * w4.z + a.w * w4.w;
    }
    __shared__ float red[128];
    red[threadIdx.x] = s;
    __syncthreads();
    for (int st = 64; st > 0; st >>= 1) {
        if (threadIdx.x < st) red[threadIdx.x] += red[threadIdx.x + st];
        __syncthreads();
    }
    if (threadIdx.x == 0)
        out[b * 512 + co] = fmaxf(red[0] + fc_b[co], 0.f);
}

// ---------------- K6: logit = emb @ logit_w^T ----------------
__global__ void logit_kernel(const float* __restrict__ emb,
                             const float* __restrict__ lw,
                             float* __restrict__ out) {
    const int b = blockIdx.y, o = blockIdx.x;
    const float4* e = (const float4*)(emb + b * 512);
    const float4* wr = (const float4*)(lw + (size_t)o * 512);
    float s = 0.f;
    for (int i = threadIdx.x; i < 128; i += 64) {
        float4 a = e[i], w4 = wr[i];
        s += a.x * w4.x + a.y * w4.y + a.z * w4.z + a.w * w4.w;
    }
    __shared__ float red[64];
    red[threadIdx.x] = s;
    __syncthreads();
    for (int st = 32; st > 0; st >>= 1) {
        if (threadIdx.x < st) red[threadIdx.x] += red[threadIdx.x + st];
        __syncthreads();
    }
    if (threadIdx.x == 0) out[b * OUT_ + o] = red[0];
}

// ---------------- launch ----------------
extern "C" void kernel_launch(void* const* d_in, const int* in_sizes, int n_in,
                              void* d_out, int out_size) {
    const float* x5        = (const float*)d_in[0];
    const float* conv_w    = (const float*)d_in[5];
    const float* conv_b    = (const float*)d_in[6];
    const float* cc_w      = (const float*)d_in[7];
    const float* cc_b      = (const float*)d_in[8];
    const float* centroids = (const float*)d_in[9];
    const float* fc_w      = (const float*)d_in[10];
    const float* fc_b      = (const float*)d_in[11];
    const float* logit_w   = (const float*)d_in[12];
    float* out = (float*)d_out;

    cudaFuncSetAttribute(conv_mma, cudaFuncAttributeMaxDynamicSharedMemorySize, SMEM_TOTAL);

    pack_kernel<<<(MPAD * KDIM + 255) / 256, 256>>>(conv_w, conv_b, cc_w, cc_b);
    init_scores<<<(B_ * SCOR_BSTR + 255) / 256, 256>>>();
    xt_kernel<<<dim3(160, 256), 256>>>(x5);
    conv_mma<<<dim3(NDIM / NT, 4), 256, SMEM_TOTAL>>>();
    score_mma<<<dim3(NDIM / NT, KSPLIT), 128, S_SMEM>>>();
    softmax_kernel<<<(NDIM + 255) / 256, 256>>>();
    asum_kernel<<<B_ * KC_, 256>>>();
    agg_kernel<<<dim3(8, B_), 256>>>();
    vlad_kernel<<<B_ * KC_, 256>>>(centroids);
    emb_kernel<<<dim3(C_, B_), 128>>>(fc_w, fc_b, out);
    logit_kernel<<<dim3(OUT_, B_), 64>>>(out, logit_w, out + B_ * C_);
}

// round 7
// speedup vs baseline: 4.0762x; 1.1051x over previous
#include <cuda_runtime.h>
#include <cuda_fp16.h>
#include <cstdint>
#include <math.h>

// ---------------- problem constants ----------------
#define B_        16
#define C_        512
#define H_        16
#define W_        300
#define HO_       10
#define KG_       10
#define KC_       8
#define OUT_      5994
#define KDIM      3584        // C_ * 7
#define NDIM      48000       // B_ * HO_ * W_
#define MPAD      640
#define MREAL     522
#define HWX       4800        // H_*W_
#define BSTR      2457600     // C_*H_*W_
#define P_        3000        // HO_*W_
#define FEAT_BSTR 1536000     // C_*P_
#define SCOR_BSTR 30000       // KG_*P_
#define XT_ROWS   (B_*H_*W_)  // 76800

// main GEMM tiling: CTA 128ch x 256pos, 8 warps (2m x 4n), warp tile 64x64
#define MT        128
#define NT        256
#define NCHUNK    112         // KDIM / 32
#define ROWB      80          // padded smem row stride (32 fp16 = 64B + 16B pad)
#define TILE_A_B  10240       // 128 rows * 80B
#define TILE_X_B  20480       // 256 rows * 80B
#define BUF_B     30720       // A | X
#define SMEM_TOTAL (2*BUF_B)  // 61440

// score GEMM: k-split
#define KSPLIT    4
#define SCHUNK    (NCHUNK / KSPLIT)   // 28
#define SNT       128
#define S_ATILE   1280        // 16 rows * 80B
#define S_BUF     11520       // A 1280 | B 10240
#define S_SMEM    (2*S_BUF)   // 23040

// ---------------- device scratch ----------------
__device__ __half g_wh[MPAD * KDIM];
__device__ float g_bias[MPAD];
__device__ __half g_xh[XT_ROWS * C_];
__device__ __half g_feats[B_ * C_ * HO_ * W_];
__device__ float g_scores[B_ * KG_ * HO_ * W_];
__device__ float g_assign[B_ * KG_ * HO_ * W_];
__device__ float g_asum[B_ * KC_];
__device__ float g_agg[B_ * KC_ * C_];
__device__ float g_vlad[B_ * KC_ * C_];

// ---------------- helpers ----------------
__device__ __forceinline__ uint32_t smem_u32(const void* p) {
    uint32_t a;
    asm("{ .reg .u64 t; cvta.to.shared.u64 t, %1; cvt.u32.u64 %0, t; }" : "=r"(a) : "l"(p));
    return a;
}
__device__ __forceinline__ void ldsm4(uint32_t* r, uint32_t addr) {
    asm volatile("ldmatrix.sync.aligned.m8n8.x4.shared.b16 {%0,%1,%2,%3}, [%4];"
                 : "=r"(r[0]), "=r"(r[1]), "=r"(r[2]), "=r"(r[3]) : "r"(addr));
}
__device__ __forceinline__ void mma_f16(float* c, const uint32_t* a, const uint32_t* b) {
    asm volatile(
        "mma.sync.aligned.m16n8k16.row.col.f32.f16.f16.f32 "
        "{%0,%1,%2,%3},{%4,%5,%6,%7},{%8,%9},{%0,%1,%2,%3};"
        : "+f"(c[0]), "+f"(c[1]), "+f"(c[2]), "+f"(c[3])
        : "r"(a[0]), "r"(a[1]), "r"(a[2]), "r"(a[3]), "r"(b[0]), "r"(b[1]));
}
#define CP_ASYNC16(s, g) \
    asm volatile("cp.async.cg.shared.global [%0], [%1], 16;" :: "r"(s), "l"(g))
#define CP_COMMIT()  asm volatile("cp.async.commit_group;" ::: "memory")
#define CP_WAIT0()   asm volatile("cp.async.wait_group 0;" ::: "memory")
#define CP_WAIT1()   asm volatile("cp.async.wait_group 1;" ::: "memory")

// ---------------- K0: pack weights (kh-major K) fp16 + bias ----------------
__global__ void pack_kernel(const float* __restrict__ conv_w,
                            const float* __restrict__ conv_b,
                            const float* __restrict__ cc_w,
                            const float* __restrict__ cc_b) {
    int i = blockIdx.x * blockDim.x + threadIdx.x;
    if (i < MPAD * KDIM) {
        int m = i / KDIM, kk = i - m * KDIM;     // kk = kh*512 + ci
        int kh = kk >> 9, ci = kk & 511;
        float v = 0.f;
        if (m < 512)      v = conv_w[m * KDIM + ci * 7 + kh];
        else if (m < 522) v = cc_w[(m - 512) * KDIM + ci * 7 + kh];
        g_wh[i] = __float2half_rn(v);
    }
    if (i < MPAD) {
        float bv = 0.f;
        if (i < 512)      bv = conv_b[i];
        else if (i < 522) bv = cc_b[i - 512];
        g_bias[i] = bv;
    }
}

// ---------------- K0c: init scores with bias (atomic accumulation target) ----
__global__ void init_scores() {
    int i = blockIdx.x * 256 + threadIdx.x;
    if (i < B_ * SCOR_BSTR) {
        int k = (i % SCOR_BSTR) / P_;
        g_scores[i] = g_bias[512 + k];
    }
}

// ---------------- K0b: transpose x -> [b,h,w,c] fp16 ----------------
__global__ void xt_kernel(const float* __restrict__ x) {
    __shared__ float xs[32][33];
    const int ct = blockIdx.x & 15;        // channel tile (16)
    const int wt = blockIdx.x >> 4;        // w tile (10)
    const int b  = blockIdx.y >> 4;
    const int h  = blockIdx.y & 15;
    const int tid = threadIdx.x;
    const float* xb = x + (size_t)b * BSTR + h * W_;
#pragma unroll
    for (int it = 0; it < 4; it++) {
        int e = tid + 256 * it;
        int c = e >> 5, w = e & 31;
        int gw = wt * 32 + w;
        xs[c][w] = (gw < W_) ? xb[(size_t)(ct * 32 + c) * HWX + gw] : 0.f;
    }
    __syncthreads();
    const size_t rowb = ((size_t)(b * 16 + h)) * W_;
#pragma unroll
    for (int it = 0; it < 4; it++) {
        int e = tid + 256 * it;
        int w = e >> 5, c = e & 31;
        int gw = wt * 32 + w;
        if (gw < W_)
            g_xh[(rowb + gw) * C_ + ct * 32 + c] = __float2half_rn(xs[c][w]);
    }
}

// ---------------- K1: feats GEMM, warp tile 64x64, cp.async double buffer ----
__global__ void __launch_bounds__(256, 1) conv_mma() {
    extern __shared__ char sm[];
    const uint32_t smb = smem_u32(sm);
    const int tid  = threadIdx.x;
    const int wid  = tid >> 5;
    const int lane = tid & 31;
    const int mBase = blockIdx.y * MT;
    const int nBase = blockIdx.x * NT;

    // ---- loader setup ----
    // A: row = tid&127, 2 x 16B chunks (c16 = it*2 + thi)
    const int arow = tid & 127;
    const int thi  = tid >> 7;
    // X: row = tid (position), 4 x 16B chunks
    int n = nBase + tid;
    if (n >= NDIM) n = NDIM - 1;     // clamp (tail CTA); stores are guarded
    const int b2  = n / P_;
    const int rem = n - b2 * P_;
    const int ho  = rem / W_;
    const int w   = rem - ho * W_;
    const size_t bRowBase = ((size_t)(b2 * 16 + ho) * W_ + w) * C_;

    const __half* aPtr[2];
    uint32_t aSoff[2];
#pragma unroll
    for (int it = 0; it < 2; it++) {
        const int c16 = it * 2 + thi;
        aPtr[it]  = g_wh + (size_t)(mBase + arow) * KDIM + c16 * 8;
        aSoff[it] = (uint32_t)(arow * ROWB + c16 * 16);
    }
    const __half* xPtr = g_xh + bRowBase;
    const uint32_t xSoff = (uint32_t)(TILE_A_B + tid * ROWB);

    // ---- per-warp ldmatrix base addresses ----
    const int mw = wid >> 2;           // 0..1
    const int nw = wid & 3;            // 0..3
    const uint32_t aAddr = (uint32_t)((mw * 64 + (lane & 15)) * ROWB + ((lane >> 4) << 4));
    const uint32_t bAddr = (uint32_t)(TILE_A_B +
                           (nw * 64 + (lane & 7) + ((lane >> 4) << 3)) * ROWB +
                           (((lane >> 3) & 1) << 4));

    float acc[4][8][4];
#pragma unroll
    for (int i = 0; i < 4; i++)
#pragma unroll
        for (int j = 0; j < 8; j++)
#pragma unroll
            for (int r = 0; r < 4; r++) acc[i][j][r] = 0.f;

    // ---- async load of one k-chunk into buffer at sbase ----
    auto issue_chunk = [&](int chunk, uint32_t sbase) {
        const int k0  = chunk << 5;
        const int kh  = k0 >> 9;
        const int ci0 = k0 & 511;
        const size_t bo = (size_t)kh * (W_ * C_) + ci0;
#pragma unroll
        for (int it = 0; it < 2; it++)
            CP_ASYNC16(sbase + aSoff[it], aPtr[it] + k0);
#pragma unroll
        for (int it = 0; it < 4; it++)
            CP_ASYNC16(sbase + xSoff + it * 16, xPtr + bo + it * 8);
    };

    issue_chunk(0, smb);
    CP_COMMIT();

#pragma unroll 1
    for (int i = 0; i < NCHUNK; i++) {
        const int cur = i & 1;
        if (i + 1 < NCHUNK) {
            issue_chunk(i + 1, smb + (uint32_t)(cur ^ 1) * BUF_B);
            CP_COMMIT();
            CP_WAIT1();
        } else {
            CP_WAIT0();
        }
        __syncthreads();
        // ---- compute on buffer cur ----
        const uint32_t base = smb + (uint32_t)cur * BUF_B;
#pragma unroll
        for (int q = 0; q < 2; q++) {
            const uint32_t qo = q * 32;
            uint32_t ah[4][4], bf[8][2];
#pragma unroll
            for (int f = 0; f < 4; f++)
                ldsm4(ah[f], base + aAddr + f * 1280 + qo);
#pragma unroll
            for (int t = 0; t < 4; t++) {
                uint32_t r[4];
                ldsm4(r, base + bAddr + t * 1280 + qo);
                bf[2 * t][0] = r[0]; bf[2 * t][1] = r[1];
                bf[2 * t + 1][0] = r[2]; bf[2 * t + 1][1] = r[3];
            }
#pragma unroll
            for (int f = 0; f < 4; f++)
#pragma unroll
                for (int j = 0; j < 8; j++)
                    mma_f16(acc[f][j], ah[f], bf[j]);
        }
        __syncthreads();
    }

    // ---- epilogue: bias + relu, fp16 stores (all m < 512), guarded tail ----
    float bias_v[4][2];
#pragma unroll
    for (int f = 0; f < 4; f++)
#pragma unroll
        for (int h = 0; h < 2; h++)
            bias_v[f][h] = g_bias[mBase + mw * 64 + f * 16 + (lane >> 2) + 8 * h];
#pragma unroll
    for (int j = 0; j < 8; j++) {
        const int nj  = nBase + nw * 64 + j * 8 + (lane & 3) * 2;
        if (nj >= NDIM) continue;
        const int bj  = nj / P_;
        const int rj  = nj - bj * P_;
        const size_t fb = (size_t)bj * FEAT_BSTR + rj;
#pragma unroll
        for (int f = 0; f < 4; f++)
#pragma unroll
            for (int h = 0; h < 2; h++) {
                const int m = mBase + mw * 64 + f * 16 + (lane >> 2) + 8 * h;
                __half2 o = __floats2half2_rn(
                    fmaxf(acc[f][j][2 * h]     + bias_v[f][h], 0.f),
                    fmaxf(acc[f][j][2 * h + 1] + bias_v[f][h], 0.f));
                *(__half2*)(g_feats + fb + (size_t)m * P_) = o;
            }
    }
}

// ---------------- K1b: scores GEMM, k-split x4 with atomic merge ----------------
__global__ void __launch_bounds__(128) score_mma() {
    extern __shared__ char sm[];
    const uint32_t smb = smem_u32(sm);
    const int tid  = threadIdx.x;
    const int wid  = tid >> 5;      // 0..3 = n-warp
    const int lane = tid & 31;
    const int nBase = blockIdx.x * SNT;
    const int cBase = blockIdx.y * SCHUNK;     // chunk segment

    // B loader: row = tid, 4 chunks
    const int n   = nBase + tid;
    const int b2  = n / P_;
    const int rem = n - b2 * P_;
    const int ho  = rem / W_;
    const int w   = rem - ho * W_;
    const size_t bRowBase = ((size_t)(b2 * 16 + ho) * W_ + w) * C_;
    // A loader: 64 transfers: 16 rows * 4 chunks (tid < 64)
    const int arow = (tid & 63) >> 2;
    const int ac16 = tid & 3;
    const bool aact = tid < 64;
    const __half* aPtr = g_wh + (size_t)(512 + arow) * KDIM + ac16 * 8;
    const uint32_t aSoff = (uint32_t)(arow * ROWB + ac16 * 16);

    const uint32_t aAddr = (uint32_t)((lane & 15) * ROWB + ((lane >> 4) << 4));
    const uint32_t bAddr = (uint32_t)(S_ATILE +
                           (wid * 32 + (lane & 7) + ((lane >> 4) << 3)) * ROWB +
                           (((lane >> 3) & 1) << 4));

    float acc[4][4];
#pragma unroll
    for (int j = 0; j < 4; j++)
#pragma unroll
        for (int r = 0; r < 4; r++) acc[j][r] = 0.f;

    // prologue: chunk cBase
    {
        const int k0  = cBase << 5;
        const int kh  = k0 >> 9;
        const int ci0 = k0 & 511;
        const size_t bo = (size_t)kh * (W_ * C_) + ci0;
        uint4 vb[4];
#pragma unroll
        for (int c = 0; c < 4; c++) vb[c] = *(const uint4*)(g_xh + bRowBase + bo + c * 8);
        if (aact) *(uint4*)(sm + aSoff) = *(const uint4*)(aPtr + k0);
#pragma unroll
        for (int c = 0; c < 4; c++)
            *(uint4*)(sm + S_ATILE + tid * ROWB + c * 16) = vb[c];
    }
    __syncthreads();

#pragma unroll 1
    for (int i = 0; i < SCHUNK; i++) {
        const int cur = i & 1;
        uint4 va, vb[4];
        const bool hasNext = (i + 1) < SCHUNK;
        if (hasNext) {
            const int k0  = (cBase + i + 1) << 5;
            const int kh  = k0 >> 9;
            const int ci0 = k0 & 511;
            const size_t bo = (size_t)kh * (W_ * C_) + ci0;
            if (aact) va = *(const uint4*)(aPtr + k0);
#pragma unroll
            for (int c = 0; c < 4; c++) vb[c] = *(const uint4*)(g_xh + bRowBase + bo + c * 8);
        }
        {
            const uint32_t base = smb + (uint32_t)cur * S_BUF;
#pragma unroll
            for (int q = 0; q < 2; q++) {
                const uint32_t qo = q * 32;
                uint32_t ah[4], bf[4][2];
                ldsm4(ah, base + aAddr + qo);
#pragma unroll
                for (int t = 0; t < 2; t++) {
                    uint32_t r[4];
                    ldsm4(r, base + bAddr + t * 1280 + qo);
                    bf[2 * t][0] = r[0]; bf[2 * t][1] = r[1];
                    bf[2 * t + 1][0] = r[2]; bf[2 * t + 1][1] = r[3];
                }
#pragma unroll
                for (int j = 0; j < 4; j++)
                    mma_f16(acc[j], ah, bf[j]);
            }
        }
        if (hasNext) {
            char* bb = sm + (cur ^ 1) * S_BUF;
            if (aact) *(uint4*)(bb + aSoff) = va;
#pragma unroll
            for (int c = 0; c < 4; c++)
                *(uint4*)(bb + S_ATILE + tid * ROWB + c * 16) = vb[c];
        }
        __syncthreads();
    }

    // epilogue: rows 0..9 real -> atomic merge into scores
#pragma unroll
    for (int j = 0; j < 4; j++) {
        const int nj  = nBase + wid * 32 + j * 8 + (lane & 3) * 2;
        const int bj  = nj / P_;
        const int rj  = nj - bj * P_;
        const size_t sb = (size_t)bj * SCOR_BSTR + rj;
#pragma unroll
        for (int h = 0; h < 2; h++) {
            const int m = (lane >> 2) + 8 * h;
            if (m < KG_) {
                atomicAdd(g_scores + sb + (size_t)m * P_,     acc[j][2 * h]);
                atomicAdd(g_scores + sb + (size_t)m * P_ + 1, acc[j][2 * h + 1]);
            }
        }
    }
}

// ---------------- K2: softmax over 10 cluster channels ----------------
__global__ void softmax_kernel() {
    int q = blockIdx.x * 256 + threadIdx.x;
    if (q >= NDIM) return;
    int b = q / P_;
    int rem = q - b * P_;
    int base = b * SCOR_BSTR + rem;
    float s[KG_];
    float mx = -1e30f;
#pragma unroll
    for (int k = 0; k < KG_; k++) { s[k] = g_scores[base + k * P_]; mx = fmaxf(mx, s[k]); }
    float sum = 0.f;
#pragma unroll
    for (int k = 0; k < KG_; k++) { s[k] = expf(s[k] - mx); sum += s[k]; }
    float inv = 1.f / sum;
#pragma unroll
    for (int k = 0; k < KG_; k++) g_assign[base + k * P_] = s[k] * inv;
}

// ---------------- K2b: asum ----------------
__global__ void asum_kernel() {
    int b = blockIdx.x >> 3, k = blockIdx.x & 7;
    const float* a = g_assign + b * SCOR_BSTR + k * P_;
    float s = 0.f;
    for (int i = threadIdx.x; i < P_; i += 256) s += a[i];
    __shared__ float red[256];
    red[threadIdx.x] = s;
    __syncthreads();
    for (int st = 128; st > 0; st >>= 1) {
        if (threadIdx.x < st) red[threadIdx.x] += red[threadIdx.x + st];
        __syncthreads();
    }
    if (threadIdx.x == 0) g_asum[blockIdx.x] = red[0];
}

// ---------------- K3: agg[b][k][c] = sum_p assign[b][k][p]*feats[b][c][p] ----------------
__global__ void agg_kernel() {
    __shared__ float fs[64][65];
    __shared__ float as[8][64];
    const int b = blockIdx.y;
    const int c0 = blockIdx.x * 64;
    const int t = threadIdx.x;
    const int k = t >> 6;
    const int c = t & 63;
    const __half* fb = g_feats + (size_t)b * FEAT_BSTR + (size_t)c0 * P_;
    const float* ab = g_assign + b * SCOR_BSTR;
    float acc0 = 0.f, acc1 = 0.f;
    for (int p0 = 0; p0 < P_; p0 += 64) {
        int pc = P_ - p0; if (pc > 64) pc = 64;
#pragma unroll
        for (int idx = t; idx < 4096; idx += 256) {
            int cc = idx >> 6, pp = idx & 63;
            fs[cc][pp] = (pp < pc) ? __half2float(fb[cc * P_ + p0 + pp]) : 0.f;
        }
#pragma unroll
        for (int idx = t; idx < 512; idx += 256) {
            int kk = idx >> 6, pp = idx & 63;
            as[kk][pp] = (pp < pc) ? ab[kk * P_ + p0 + pp] : 0.f;
        }
        __syncthreads();
#pragma unroll
        for (int p = 0; p < 64; p++) {
            float f = fs[c][p];
            acc0 = fmaf(as[k][p], f, acc0);
            acc1 = fmaf(as[k + 4][p], f, acc1);
        }
        __syncthreads();
    }
    g_agg[b * 4096 + k * 512 + c0 + c] = acc0;
    g_agg[b * 4096 + (k + 4) * 512 + c0 + c] = acc1;
}

// ---------------- K4: residual + L2 normalize ----------------
__global__ void vlad_kernel(const float* __restrict__ centroids) {
    const int b = blockIdx.x >> 3, k = blockIdx.x & 7;
    const int t = threadIdx.x;
    const float asum = g_asum[blockIdx.x];
    const float* aggp = g_agg + b * 4096 + k * 512;
    const float* cen = centroids + k * 512;
    float r0 = aggp[t] - asum * cen[t];
    float r1 = aggp[t + 256] - asum * cen[t + 256];
    __shared__ float red[256];
    red[t] = r0 * r0 + r1 * r1;
    __syncthreads();
    for (int st = 128; st > 0; st >>= 1) {
        if (t < st) red[t] += red[t + st];
        __syncthreads();
    }
    __shared__ float scale_s;
    if (t == 0) scale_s = 1.f / fmaxf(sqrtf(red[0]), 1e-12f);
    __syncthreads();
    float sc = scale_s;
    g_vlad[b * 4096 + k * 512 + t] = r0 * sc;
    g_vlad[b * 4096 + k * 512 + t + 256] = r1 * sc;
}

// ---------------- K5: emb = relu(vlad @ fc_w^T + fc_b) ----------------
__global__ void emb_kernel(const float* __restrict__ fc_w,
                           const float* __restrict__ fc_b,
                           float* __restrict__ out) {
    const int b = blockIdx.y, co = blockIdx.x;
    const float4* v = (const float4*)(g_vlad + b * 4096);
    const float4* wr = (const float4*)(fc_w + (size_t)co * 4096);
    float s = 0.f;
    for (int i = threadIdx.x; i < 1024; i += 128) {
        float4 a = v[i], w4 = wr[i];
        s += a.x * w4.x + a.y * w4.y + a.z * w4.z + a.w * w4.w;
    }
    __shared__ float red[128];
    red[threadIdx.x] = s;
    __syncthreads();
    for (int st = 64; st > 0; st >>= 1) {
        if (threadIdx.x < st) red[threadIdx.x] += red[threadIdx.x + st];
        __syncthreads();
    }
    if (threadIdx.x == 0)
        out[b * 512 + co] = fmaxf(red[0] + fc_b[co], 0.f);
}

// ---------------- K6: logit = emb @ logit_w^T ----------------
__global__ void logit_kernel(const float* __restrict__ emb,
                             const float* __restrict__ lw,
                             float* __restrict__ out) {
    const int b = blockIdx.y, o = blockIdx.x;
    const float4* e = (const float4*)(emb + b * 512);
    const float4* wr = (const float4*)(lw + (size_t)o * 512);
    float s = 0.f;
    for (int i = threadIdx.x; i < 128; i += 64) {
        float4 a = e[i], w4 = wr[i];
        s += a.x * w4.x + a.y * w4.y + a.z * w4.z + a.w * w4.w;
    }
    __shared__ float red[64];
    red[threadIdx.x] = s;
    __syncthreads();
    for (int st = 32; st > 0; st >>= 1) {
        if (threadIdx.x < st) red[threadIdx.x] += red[threadIdx.x + st];
        __syncthreads();
    }
    if (threadIdx.x == 0) out[b * OUT_ + o] = red[0];
}

// ---------------- launch ----------------
extern "C" void kernel_launch(void* const* d_in, const int* in_sizes, int n_in,
                              void* d_out, int out_size) {
    const float* x5        = (const float*)d_in[0];
    const float* conv_w    = (const float*)d_in[5];
    const float* conv_b    = (const float*)d_in[6];
    const float* cc_w      = (const float*)d_in[7];
    const float* cc_b      = (const float*)d_in[8];
    const float* centroids = (const float*)d_in[9];
    const float* fc_w      = (const float*)d_in[10];
    const float* fc_b      = (const float*)d_in[11];
    const float* logit_w   = (const float*)d_in[12];
    float* out = (float*)d_out;

    cudaFuncSetAttribute(conv_mma, cudaFuncAttributeMaxDynamicSharedMemorySize, SMEM_TOTAL);

    pack_kernel<<<(MPAD * KDIM + 255) / 256, 256>>>(conv_w, conv_b, cc_w, cc_b);
    init_scores<<<(B_ * SCOR_BSTR + 255) / 256, 256>>>();
    xt_kernel<<<dim3(160, 256), 256>>>(x5);
    conv_mma<<<dim3((NDIM + NT - 1) / NT, 4), 256, SMEM_TOTAL>>>();
    score_mma<<<dim3(NDIM / SNT, KSPLIT), 128, S_SMEM>>>();
    softmax_kernel<<<(NDIM + 255) / 256, 256>>>();
    asum_kernel<<<B_ * KC_, 256>>>();
    agg_kernel<<<dim3(8, B_), 256>>>();
    vlad_kernel<<<B_ * KC_, 256>>>(centroids);
    emb_kernel<<<dim3(C_, B_), 128>>>(fc_w, fc_b, out);
    logit_kernel<<<dim3(OUT_, B_), 64>>>(out, logit_w, out + B_ * C_);
}

// round 8
// speedup vs baseline: 4.3829x; 1.0752x over previous
#include <cuda_runtime.h>
#include <cuda_fp16.h>
#include <cstdint>
#include <math.h>

// ---------------- problem constants ----------------
#define B_        16
#define C_        512
#define H_        16
#define W_        300
#define HO_       10
#define KG_       10
#define KC_       8
#define OUT_      5994
#define KDIM      3584        // C_ * 7
#define NDIM      48000       // B_ * HO_ * W_
#define MPAD      640
#define MREAL     522
#define HWX       4800        // H_*W_
#define BSTR      2457600     // C_*H_*W_
#define P_        3000        // HO_*W_
#define FEAT_BSTR 1536000     // C_*P_
#define SCOR_BSTR 30000       // KG_*P_
#define XT_ROWS   (B_*H_*W_)  // 76800

// main GEMM tiling: CTA 128ch x 128pos, 4 warps (2m x 2n), warp tile 64x64
#define MT        128
#define NT        128
#define NCHUNK    112         // KDIM / 32
#define STAGES    4
#define ROWB      80          // padded smem row stride (32 fp16 = 64B + 16B pad)
#define TILE_A_B  10240       // 128 rows * 80B
#define BUF_B     20480       // A | X
#define SMEM_TOTAL (STAGES*BUF_B)  // 81920

// score GEMM: k-split
#define KSPLIT    4
#define SCHUNK    (NCHUNK / KSPLIT)   // 28
#define SNT       128
#define S_ATILE   1280        // 16 rows * 80B
#define S_BUF     11520       // A 1280 | B 10240
#define S_SMEM    (2*S_BUF)   // 23040

// ---------------- device scratch ----------------
__device__ __half g_wh[MPAD * KDIM];
__device__ float g_bias[MPAD];
__device__ __half g_xh[XT_ROWS * C_];
__device__ __half g_feats[B_ * C_ * HO_ * W_];
__device__ float g_scores[B_ * KG_ * HO_ * W_];
__device__ float g_assign[B_ * KG_ * HO_ * W_];
__device__ float g_asum[B_ * KC_];
__device__ float g_agg[B_ * KC_ * C_];
__device__ float g_vlad[B_ * KC_ * C_];

// ---------------- helpers ----------------
__device__ __forceinline__ uint32_t smem_u32(const void* p) {
    uint32_t a;
    asm("{ .reg .u64 t; cvta.to.shared.u64 t, %1; cvt.u32.u64 %0, t; }" : "=r"(a) : "l"(p));
    return a;
}
__device__ __forceinline__ void ldsm4(uint32_t* r, uint32_t addr) {
    asm volatile("ldmatrix.sync.aligned.m8n8.x4.shared.b16 {%0,%1,%2,%3}, [%4];"
                 : "=r"(r[0]), "=r"(r[1]), "=r"(r[2]), "=r"(r[3]) : "r"(addr));
}
__device__ __forceinline__ void mma_f16(float* c, const uint32_t* a, const uint32_t* b) {
    asm volatile(
        "mma.sync.aligned.m16n8k16.row.col.f32.f16.f16.f32 "
        "{%0,%1,%2,%3},{%4,%5,%6,%7},{%8,%9},{%0,%1,%2,%3};"
        : "+f"(c[0]), "+f"(c[1]), "+f"(c[2]), "+f"(c[3])
        : "r"(a[0]), "r"(a[1]), "r"(a[2]), "r"(a[3]), "r"(b[0]), "r"(b[1]));
}
#define CP_ASYNC16(s, g) \
    asm volatile("cp.async.cg.shared.global [%0], [%1], 16;" :: "r"(s), "l"(g))
#define CP_COMMIT()  asm volatile("cp.async.commit_group;" ::: "memory")
#define CP_WAIT0()   asm volatile("cp.async.wait_group 0;" ::: "memory")
#define CP_WAIT1()   asm volatile("cp.async.wait_group 1;" ::: "memory")
#define CP_WAIT2()   asm volatile("cp.async.wait_group 2;" ::: "memory")

// ---------------- K0: pack weights (kh-major K) fp16 + bias ----------------
__global__ void pack_kernel(const float* __restrict__ conv_w,
                            const float* __restrict__ conv_b,
                            const float* __restrict__ cc_w,
                            const float* __restrict__ cc_b) {
    int i = blockIdx.x * blockDim.x + threadIdx.x;
    if (i < MPAD * KDIM) {
        int m = i / KDIM, kk = i - m * KDIM;     // kk = kh*512 + ci
        int kh = kk >> 9, ci = kk & 511;
        float v = 0.f;
        if (m < 512)      v = conv_w[m * KDIM + ci * 7 + kh];
        else if (m < 522) v = cc_w[(m - 512) * KDIM + ci * 7 + kh];
        g_wh[i] = __float2half_rn(v);
    }
    if (i < MPAD) {
        float bv = 0.f;
        if (i < 512)      bv = conv_b[i];
        else if (i < 522) bv = cc_b[i - 512];
        g_bias[i] = bv;
    }
}

// ---------------- K0c: init scores with bias (atomic accumulation target) ----
__global__ void init_scores() {
    int i = blockIdx.x * 256 + threadIdx.x;
    if (i < B_ * SCOR_BSTR) {
        int k = (i % SCOR_BSTR) / P_;
        g_scores[i] = g_bias[512 + k];
    }
}

// ---------------- K0b: transpose x -> [b,h,w,c] fp16 ----------------
__global__ void xt_kernel(const float* __restrict__ x) {
    __shared__ float xs[32][33];
    const int ct = blockIdx.x & 15;        // channel tile (16)
    const int wt = blockIdx.x >> 4;        // w tile (10)
    const int b  = blockIdx.y >> 4;
    const int h  = blockIdx.y & 15;
    const int tid = threadIdx.x;
    const float* xb = x + (size_t)b * BSTR + h * W_;
#pragma unroll
    for (int it = 0; it < 4; it++) {
        int e = tid + 256 * it;
        int c = e >> 5, w = e & 31;
        int gw = wt * 32 + w;
        xs[c][w] = (gw < W_) ? xb[(size_t)(ct * 32 + c) * HWX + gw] : 0.f;
    }
    __syncthreads();
    const size_t rowb = ((size_t)(b * 16 + h)) * W_;
#pragma unroll
    for (int it = 0; it < 4; it++) {
        int e = tid + 256 * it;
        int w = e >> 5, c = e & 31;
        int gw = wt * 32 + w;
        if (gw < W_)
            g_xh[(rowb + gw) * C_ + ct * 32 + c] = __float2half_rn(xs[c][w]);
    }
}

// ---------------- K1: feats GEMM, 4-stage cp.async, 2 CTAs/SM ----------------
__global__ void __launch_bounds__(128, 2) conv_mma() {
    extern __shared__ char sm[];
    const uint32_t smb = smem_u32(sm);
    const int tid  = threadIdx.x;
    const int wid  = tid >> 5;
    const int lane = tid & 31;
    const int mBase = blockIdx.y * MT;
    const int nBase = blockIdx.x * NT;

    // ---- loader setup: each thread owns one A row + one X row, 4 chunks each ----
    const int n   = nBase + tid;
    const int b2  = n / P_;
    const int rem = n - b2 * P_;
    const int ho  = rem / W_;
    const int w   = rem - ho * W_;
    const size_t bRowBase = ((size_t)(b2 * 16 + ho) * W_ + w) * C_;
    const __half* aPtr = g_wh + (size_t)(mBase + tid) * KDIM;
    const __half* xPtr = g_xh + bRowBase;
    const uint32_t aSoff = (uint32_t)(tid * ROWB);
    const uint32_t xSoff = (uint32_t)(TILE_A_B + tid * ROWB);

    // ---- per-warp ldmatrix base addresses (2m x 2n warps, 64x64 tiles) ----
    const int mw = wid >> 1;
    const int nw = wid & 1;
    const uint32_t aAddr = (uint32_t)((mw * 64 + (lane & 15)) * ROWB + ((lane >> 4) << 4));
    const uint32_t bAddr = (uint32_t)(TILE_A_B +
                           (nw * 64 + (lane & 7) + ((lane >> 4) << 3)) * ROWB +
                           (((lane >> 3) & 1) << 4));

    float acc[4][8][4];
#pragma unroll
    for (int i = 0; i < 4; i++)
#pragma unroll
        for (int j = 0; j < 8; j++)
#pragma unroll
            for (int r = 0; r < 4; r++) acc[i][j][r] = 0.f;

    auto issue_chunk = [&](int chunk, uint32_t sbase) {
        const int k0  = chunk << 5;
        const int kh  = k0 >> 9;
        const int ci0 = k0 & 511;
        const size_t bo = (size_t)kh * (W_ * C_) + ci0;
#pragma unroll
        for (int c = 0; c < 4; c++)
            CP_ASYNC16(sbase + aSoff + c * 16, aPtr + k0 + c * 8);
#pragma unroll
        for (int c = 0; c < 4; c++)
            CP_ASYNC16(sbase + xSoff + c * 16, xPtr + bo + c * 8);
    };

    // prologue: stages 0..2 in flight
#pragma unroll
    for (int s = 0; s < STAGES - 1; s++) {
        issue_chunk(s, smb + (uint32_t)s * BUF_B);
        CP_COMMIT();
    }

#pragma unroll 1
    for (int i = 0; i < NCHUNK; i++) {
        CP_WAIT2();              // chunk i resident (2 newer groups outstanding)
        __syncthreads();
        const uint32_t base = smb + (uint32_t)(i & 3) * BUF_B;
#pragma unroll
        for (int q = 0; q < 2; q++) {
            const uint32_t qo = q * 32;
            uint32_t ah[4][4], bf[8][2];
#pragma unroll
            for (int f = 0; f < 4; f++)
                ldsm4(ah[f], base + aAddr + f * 1280 + qo);
#pragma unroll
            for (int t = 0; t < 4; t++) {
                uint32_t r[4];
                ldsm4(r, base + bAddr + t * 1280 + qo);
                bf[2 * t][0] = r[0]; bf[2 * t][1] = r[1];
                bf[2 * t + 1][0] = r[2]; bf[2 * t + 1][1] = r[3];
            }
#pragma unroll
            for (int f = 0; f < 4; f++)
#pragma unroll
                for (int j = 0; j < 8; j++)
                    mma_f16(acc[f][j], ah[f], bf[j]);
        }
        if (i + STAGES - 1 < NCHUNK)
            issue_chunk(i + STAGES - 1, smb + (uint32_t)((i + STAGES - 1) & 3) * BUF_B);
        CP_COMMIT();             // always commit: keeps group count uniform
    }

    // ---- epilogue: bias + relu, fp16 stores (all m < 512) ----
    float bias_v[4][2];
#pragma unroll
    for (int f = 0; f < 4; f++)
#pragma unroll
        for (int h = 0; h < 2; h++)
            bias_v[f][h] = g_bias[mBase + mw * 64 + f * 16 + (lane >> 2) + 8 * h];
#pragma unroll
    for (int j = 0; j < 8; j++) {
        const int nj  = nBase + nw * 64 + j * 8 + (lane & 3) * 2;
        const int bj  = nj / P_;
        const int rj  = nj - bj * P_;
        const size_t fb = (size_t)bj * FEAT_BSTR + rj;
#pragma unroll
        for (int f = 0; f < 4; f++)
#pragma unroll
            for (int h = 0; h < 2; h++) {
                const int m = mBase + mw * 64 + f * 16 + (lane >> 2) + 8 * h;
                __half2 o = __floats2half2_rn(
                    fmaxf(acc[f][j][2 * h]     + bias_v[f][h], 0.f),
                    fmaxf(acc[f][j][2 * h + 1] + bias_v[f][h], 0.f));
                *(__half2*)(g_feats + fb + (size_t)m * P_) = o;
            }
    }
}

// ---------------- K1b: scores GEMM, k-split x4 with atomic merge ----------------
__global__ void __launch_bounds__(128) score_mma() {
    extern __shared__ char sm[];
    const uint32_t smb = smem_u32(sm);
    const int tid  = threadIdx.x;
    const int wid  = tid >> 5;      // 0..3 = n-warp
    const int lane = tid & 31;
    const int nBase = blockIdx.x * SNT;
    const int cBase = blockIdx.y * SCHUNK;     // chunk segment

    // B loader: row = tid, 4 chunks
    const int n   = nBase + tid;
    const int b2  = n / P_;
    const int rem = n - b2 * P_;
    const int ho  = rem / W_;
    const int w   = rem - ho * W_;
    const size_t bRowBase = ((size_t)(b2 * 16 + ho) * W_ + w) * C_;
    // A loader: 64 transfers: 16 rows * 4 chunks (tid < 64)
    const int arow = (tid & 63) >> 2;
    const int ac16 = tid & 3;
    const bool aact = tid < 64;
    const __half* aPtr = g_wh + (size_t)(512 + arow) * KDIM + ac16 * 8;
    const uint32_t aSoff = (uint32_t)(arow * ROWB + ac16 * 16);

    const uint32_t aAddr = (uint32_t)((lane & 15) * ROWB + ((lane >> 4) << 4));
    const uint32_t bAddr = (uint32_t)(S_ATILE +
                           (wid * 32 + (lane & 7) + ((lane >> 4) << 3)) * ROWB +
                           (((lane >> 3) & 1) << 4));

    float acc[4][4];
#pragma unroll
    for (int j = 0; j < 4; j++)
#pragma unroll
        for (int r = 0; r < 4; r++) acc[j][r] = 0.f;

    // prologue: chunk cBase
    {
        const int k0  = cBase << 5;
        const int kh  = k0 >> 9;
        const int ci0 = k0 & 511;
        const size_t bo = (size_t)kh * (W_ * C_) + ci0;
        uint4 vb[4];
#pragma unroll
        for (int c = 0; c < 4; c++) vb[c] = *(const uint4*)(g_xh + bRowBase + bo + c * 8);
        if (aact) *(uint4*)(sm + aSoff) = *(const uint4*)(aPtr + k0);
#pragma unroll
        for (int c = 0; c < 4; c++)
            *(uint4*)(sm + S_ATILE + tid * ROWB + c * 16) = vb[c];
    }
    __syncthreads();

#pragma unroll 1
    for (int i = 0; i < SCHUNK; i++) {
        const int cur = i & 1;
        uint4 va, vb[4];
        const bool hasNext = (i + 1) < SCHUNK;
        if (hasNext) {
            const int k0  = (cBase + i + 1) << 5;
            const int kh  = k0 >> 9;
            const int ci0 = k0 & 511;
            const size_t bo = (size_t)kh * (W_ * C_) + ci0;
            if (aact) va = *(const uint4*)(aPtr + k0);
#pragma unroll
            for (int c = 0; c < 4; c++) vb[c] = *(const uint4*)(g_xh + bRowBase + bo + c * 8);
        }
        {
            const uint32_t base = smb + (uint32_t)cur * S_BUF;
#pragma unroll
            for (int q = 0; q < 2; q++) {
                const uint32_t qo = q * 32;
                uint32_t ah[4], bf[4][2];
                ldsm4(ah, base + aAddr + qo);
#pragma unroll
                for (int t = 0; t < 2; t++) {
                    uint32_t r[4];
                    ldsm4(r, base + bAddr + t * 1280 + qo);
                    bf[2 * t][0] = r[0]; bf[2 * t][1] = r[1];
                    bf[2 * t + 1][0] = r[2]; bf[2 * t + 1][1] = r[3];
                }
#pragma unroll
                for (int j = 0; j < 4; j++)
                    mma_f16(acc[j], ah, bf[j]);
            }
        }
        if (hasNext) {
            char* bb = sm + (cur ^ 1) * S_BUF;
            if (aact) *(uint4*)(bb + aSoff) = va;
#pragma unroll
            for (int c = 0; c < 4; c++)
                *(uint4*)(bb + S_ATILE + tid * ROWB + c * 16) = vb[c];
        }
        __syncthreads();
    }

    // epilogue: rows 0..9 real -> atomic merge into scores
#pragma unroll
    for (int j = 0; j < 4; j++) {
        const int nj  = nBase + wid * 32 + j * 8 + (lane & 3) * 2;
        const int bj  = nj / P_;
        const int rj  = nj - bj * P_;
        const size_t sb = (size_t)bj * SCOR_BSTR + rj;
#pragma unroll
        for (int h = 0; h < 2; h++) {
            const int m = (lane >> 2) + 8 * h;
            if (m < KG_) {
                atomicAdd(g_scores + sb + (size_t)m * P_,     acc[j][2 * h]);
                atomicAdd(g_scores + sb + (size_t)m * P_ + 1, acc[j][2 * h + 1]);
            }
        }
    }
}

// ---------------- K2: softmax over 10 cluster channels ----------------
__global__ void softmax_kernel() {
    int q = blockIdx.x * 256 + threadIdx.x;
    if (q >= NDIM) return;
    int b = q / P_;
    int rem = q - b * P_;
    int base = b * SCOR_BSTR + rem;
    float s[KG_];
    float mx = -1e30f;
#pragma unroll
    for (int k = 0; k < KG_; k++) { s[k] = g_scores[base + k * P_]; mx = fmaxf(mx, s[k]); }
    float sum = 0.f;
#pragma unroll
    for (int k = 0; k < KG_; k++) { s[k] = expf(s[k] - mx); sum += s[k]; }
    float inv = 1.f / sum;
#pragma unroll
    for (int k = 0; k < KG_; k++) g_assign[base + k * P_] = s[k] * inv;
}

// ---------------- K2b: asum ----------------
__global__ void asum_kernel() {
    int b = blockIdx.x >> 3, k = blockIdx.x & 7;
    const float* a = g_assign + b * SCOR_BSTR + k * P_;
    float s = 0.f;
    for (int i = threadIdx.x; i < P_; i += 256) s += a[i];
    __shared__ float red[256];
    red[threadIdx.x] = s;
    __syncthreads();
    for (int st = 128; st > 0; st >>= 1) {
        if (threadIdx.x < st) red[threadIdx.x] += red[threadIdx.x + st];
        __syncthreads();
    }
    if (threadIdx.x == 0) g_asum[blockIdx.x] = red[0];
}

// ---------------- K3: agg[b][k][c] = sum_p assign[b][k][p]*feats[b][c][p] ----------------
__global__ void agg_kernel() {
    __shared__ float fs[64][65];
    __shared__ float as[8][64];
    const int b = blockIdx.y;
    const int c0 = blockIdx.x * 64;
    const int t = threadIdx.x;
    const int k = t >> 6;
    const int c = t & 63;
    const __half* fb = g_feats + (size_t)b * FEAT_BSTR + (size_t)c0 * P_;
    const float* ab = g_assign + b * SCOR_BSTR;
    float acc0 = 0.f, acc1 = 0.f;
    for (int p0 = 0; p0 < P_; p0 += 64) {
        int pc = P_ - p0; if (pc > 64) pc = 64;
#pragma unroll
        for (int idx = t; idx < 4096; idx += 256) {
            int cc = idx >> 6, pp = idx & 63;
            fs[cc][pp] = (pp < pc) ? __half2float(fb[cc * P_ + p0 + pp]) : 0.f;
        }
#pragma unroll
        for (int idx = t; idx < 512; idx += 256) {
            int kk = idx >> 6, pp = idx & 63;
            as[kk][pp] = (pp < pc) ? ab[kk * P_ + p0 + pp] : 0.f;
        }
        __syncthreads();
#pragma unroll
        for (int p = 0; p < 64; p++) {
            float f = fs[c][p];
            acc0 = fmaf(as[k][p], f, acc0);
            acc1 = fmaf(as[k + 4][p], f, acc1);
        }
        __syncthreads();
    }
    g_agg[b * 4096 + k * 512 + c0 + c] = acc0;
    g_agg[b * 4096 + (k + 4) * 512 + c0 + c] = acc1;
}

// ---------------- K4: residual + L2 normalize ----------------
__global__ void vlad_kernel(const float* __restrict__ centroids) {
    const int b = blockIdx.x >> 3, k = blockIdx.x & 7;
    const int t = threadIdx.x;
    const float asum = g_asum[blockIdx.x];
    const float* aggp = g_agg + b * 4096 + k * 512;
    const float* cen = centroids + k * 512;
    float r0 = aggp[t] - asum * cen[t];
    float r1 = aggp[t + 256] - asum * cen[t + 256];
    __shared__ float red[256];
    red[t] = r0 * r0 + r1 * r1;
    __syncthreads();
    for (int st = 128; st > 0; st >>= 1) {
        if (t < st) red[t] += red[t + st];
        __syncthreads();
    }
    __shared__ float scale_s;
    if (t == 0) scale_s = 1.f / fmaxf(sqrtf(red[0]), 1e-12f);
    __syncthreads();
    float sc = scale_s;
    g_vlad[b * 4096 + k * 512 + t] = r0 * sc;
    g_vlad[b * 4096 + k * 512 + t + 256] = r1 * sc;
}

// ---------------- K5: emb = relu(vlad @ fc_w^T + fc_b) ----------------
__global__ void emb_kernel(const float* __restrict__ fc_w,
                           const float* __restrict__ fc_b,
                           float* __restrict__ out) {
    const int b = blockIdx.y, co = blockIdx.x;
    const float4* v = (const float4*)(g_vlad + b * 4096);
    const float4* wr = (const float4*)(fc_w + (size_t)co * 4096);
    float s = 0.f;
    for (int i = threadIdx.x; i < 1024; i += 128) {
        float4 a = v[i], w4 = wr[i];
        s += a.x * w4.x + a.y * w4.y + a.z * w4.z + a.w * w4.w;
    }
    __shared__ float red[128];
    red[threadIdx.x] = s;
    __syncthreads();
    for (int st = 64; st > 0; st >>= 1) {
        if (threadIdx.x < st) red[threadIdx.x] += red[threadIdx.x + st];
        __syncthreads();
    }
    if (threadIdx.x == 0)
        out[b * 512 + co] = fmaxf(red[0] + fc_b[co], 0.f);
}

// ---------------- K6: logit = emb @ logit_w^T ----------------
__global__ void logit_kernel(const float* __restrict__ emb,
                             const float* __restrict__ lw,
                             float* __restrict__ out) {
    const int b = blockIdx.y, o = blockIdx.x;
    const float4* e = (const float4*)(emb + b * 512);
    const float4* wr = (const float4*)(lw + (size_t)o * 512);
    float s = 0.f;
    for (int i = threadIdx.x; i < 128; i += 64) {
        float4 a = e[i], w4 = wr[i];
        s += a.x * w4.x + a.y * w4.y + a.z * w4.z + a.w * w4.w;
    }
    __shared__ float red[64];
    red[threadIdx.x] = s;
    __syncthreads();
    for (int st = 32; st > 0; st >>= 1) {
        if (threadIdx.x < st) red[threadIdx.x] += red[threadIdx.x + st];
        __syncthreads();
    }
    if (threadIdx.x == 0) out[b * OUT_ + o] = red[0];
}

// ---------------- launch ----------------
extern "C" void kernel_launch(void* const* d_in, const int* in_sizes, int n_in,
                              void* d_out, int out_size) {
    const float* x5        = (const float*)d_in[0];
    const float* conv_w    = (const float*)d_in[5];
    const float* conv_b    = (const float*)d_in[6];
    const float* cc_w      = (const float*)d_in[7];
    const float* cc_b      = (const float*)d_in[8];
    const float* centroids = (const float*)d_in[9];
    const float* fc_w      = (const float*)d_in[10];
    const float* fc_b      = (const float*)d_in[11];
    const float* logit_w   = (const float*)d_in[12];
    float* out = (float*)d_out;

    cudaFuncSetAttribute(conv_mma, cudaFuncAttributeMaxDynamicSharedMemorySize, SMEM_TOTAL);

    pack_kernel<<<(MPAD * KDIM + 255) / 256, 256>>>(conv_w, conv_b, cc_w, cc_b);
    init_scores<<<(B_ * SCOR_BSTR + 255) / 256, 256>>>();
    xt_kernel<<<dim3(160, 256), 256>>>(x5);
    conv_mma<<<dim3(NDIM / NT, 4), 128, SMEM_TOTAL>>>();
    score_mma<<<dim3(NDIM / SNT, KSPLIT), 128, S_SMEM>>>();
    softmax_kernel<<<(NDIM + 255) / 256, 256>>>();
    asum_kernel<<<B_ * KC_, 256>>>();
    agg_kernel<<<dim3(8, B_), 256>>>();
    vlad_kernel<<<B_ * KC_, 256>>>(centroids);
    emb_kernel<<<dim3(C_, B_), 128>>>(fc_w, fc_b, out);
    logit_kernel<<<dim3(OUT_, B_), 64>>>(out, logit_w, out + B_ * C_);
}

// round 9
// speedup vs baseline: 4.7052x; 1.0735x over previous
#include <cuda_runtime.h>
#include <cuda_fp16.h>
#include <cstdint>
#include <math.h>

// ---------------- problem constants ----------------
#define B_        16
#define C_        512
#define H_        16
#define W_        300
#define HO_       10
#define KG_       10
#define KC_       8
#define OUT_      5994
#define KDIM      3584        // C_ * 7
#define NDIM      48000       // B_ * HO_ * W_
#define MPAD      640
#define MREAL     522
#define HWX       4800        // H_*W_
#define BSTR      2457600     // C_*H_*W_
#define P_        3000        // HO_*W_
#define FEAT_BSTR 1536000     // C_*P_
#define SCOR_BSTR 30000       // KG_*P_
#define XT_ROWS   (B_*H_*W_)  // 76800

// main GEMM tiling: CTA 128ch x 256pos, 8 warps (2m x 4n), warp tile 64x64
#define MT        128
#define NT        256
#define NCHUNK    112         // KDIM / 32
#define STAGES    4
#define ROWB      80          // padded smem row stride (32 fp16 = 64B + 16B pad)
#define TILE_A_B  10240       // 128 rows * 80B
#define TILE_X_B  20480       // 256 rows * 80B
#define BUF_B     30720       // A | X
#define SMEM_TOTAL (STAGES*BUF_B)  // 122880

// score GEMM: k-split
#define KSPLIT    4
#define SCHUNK    (NCHUNK / KSPLIT)   // 28
#define SNT       128
#define S_ATILE   1280        // 16 rows * 80B
#define S_BUF     11520       // A 1280 | B 10240
#define S_SMEM    (2*S_BUF)   // 23040

// ---------------- device scratch ----------------
__device__ __half g_wh[MPAD * KDIM];
__device__ float g_bias[MPAD];
__device__ __half g_xh[XT_ROWS * C_];
__device__ __half g_feats[B_ * C_ * HO_ * W_];
__device__ float g_scores[B_ * KG_ * HO_ * W_];
__device__ float g_assign[B_ * KG_ * HO_ * W_];
__device__ float g_asum[B_ * KC_];
__device__ float g_agg[B_ * KC_ * C_];
__device__ float g_vlad[B_ * KC_ * C_];

// ---------------- helpers ----------------
__device__ __forceinline__ uint32_t smem_u32(const void* p) {
    uint32_t a;
    asm("{ .reg .u64 t; cvta.to.shared.u64 t, %1; cvt.u32.u64 %0, t; }" : "=r"(a) : "l"(p));
    return a;
}
__device__ __forceinline__ void ldsm4(uint32_t* r, uint32_t addr) {
    asm volatile("ldmatrix.sync.aligned.m8n8.x4.shared.b16 {%0,%1,%2,%3}, [%4];"
                 : "=r"(r[0]), "=r"(r[1]), "=r"(r[2]), "=r"(r[3]) : "r"(addr));
}
__device__ __forceinline__ void mma_f16(float* c, const uint32_t* a, const uint32_t* b) {
    asm volatile(
        "mma.sync.aligned.m16n8k16.row.col.f32.f16.f16.f32 "
        "{%0,%1,%2,%3},{%4,%5,%6,%7},{%8,%9},{%0,%1,%2,%3};"
        : "+f"(c[0]), "+f"(c[1]), "+f"(c[2]), "+f"(c[3])
        : "r"(a[0]), "r"(a[1]), "r"(a[2]), "r"(a[3]), "r"(b[0]), "r"(b[1]));
}
#define CP_ASYNC16(s, g) \
    asm volatile("cp.async.cg.shared.global [%0], [%1], 16;" :: "r"(s), "l"(g))
#define CP_COMMIT()  asm volatile("cp.async.commit_group;" ::: "memory")
#define CP_WAIT0()   asm volatile("cp.async.wait_group 0;" ::: "memory")
#define CP_WAIT2()   asm volatile("cp.async.wait_group 2;" ::: "memory")

// ---------------- K0: pack weights (kh-major K) fp16 + bias ----------------
__global__ void pack_kernel(const float* __restrict__ conv_w,
                            const float* __restrict__ conv_b,
                            const float* __restrict__ cc_w,
                            const float* __restrict__ cc_b) {
    int i = blockIdx.x * blockDim.x + threadIdx.x;
    if (i < MPAD * KDIM) {
        int m = i / KDIM, kk = i - m * KDIM;     // kk = kh*512 + ci
        int kh = kk >> 9, ci = kk & 511;
        float v = 0.f;
        if (m < 512)      v = conv_w[m * KDIM + ci * 7 + kh];
        else if (m < 522) v = cc_w[(m - 512) * KDIM + ci * 7 + kh];
        g_wh[i] = __float2half_rn(v);
    }
    if (i < MPAD) {
        float bv = 0.f;
        if (i < 512)      bv = conv_b[i];
        else if (i < 522) bv = cc_b[i - 512];
        g_bias[i] = bv;
    }
}

// ---------------- K0c: init scores with bias (atomic accumulation target) ----
__global__ void init_scores() {
    int i = blockIdx.x * 256 + threadIdx.x;
    if (i < B_ * SCOR_BSTR) {
        int k = (i % SCOR_BSTR) / P_;
        g_scores[i] = g_bias[512 + k];
    }
}

// ---------------- K0b: transpose x -> [b,h,w,c] fp16 ----------------
__global__ void xt_kernel(const float* __restrict__ x) {
    __shared__ float xs[32][33];
    const int ct = blockIdx.x & 15;        // channel tile (16)
    const int wt = blockIdx.x >> 4;        // w tile (10)
    const int b  = blockIdx.y >> 4;
    const int h  = blockIdx.y & 15;
    const int tid = threadIdx.x;
    const float* xb = x + (size_t)b * BSTR + h * W_;
#pragma unroll
    for (int it = 0; it < 4; it++) {
        int e = tid + 256 * it;
        int c = e >> 5, w = e & 31;
        int gw = wt * 32 + w;
        xs[c][w] = (gw < W_) ? xb[(size_t)(ct * 32 + c) * HWX + gw] : 0.f;
    }
    __syncthreads();
    const size_t rowb = ((size_t)(b * 16 + h)) * W_;
#pragma unroll
    for (int it = 0; it < 4; it++) {
        int e = tid + 256 * it;
        int w = e >> 5, c = e & 31;
        int gw = wt * 32 + w;
        if (gw < W_)
            g_xh[(rowb + gw) * C_ + ct * 32 + c] = __float2half_rn(xs[c][w]);
    }
}

// ---------------- K1: feats GEMM, 128x256 tile, 4-stage cp.async ----------------
__global__ void __launch_bounds__(256, 1) conv_mma() {
    extern __shared__ char sm[];
    const uint32_t smb = smem_u32(sm);
    const int tid  = threadIdx.x;
    const int wid  = tid >> 5;
    const int lane = tid & 31;
    const int mBase = blockIdx.y * MT;
    const int nBase = blockIdx.x * NT;

    // ---- loader setup ----
    // A: row = tid&127, 2 x 16B chunks (c16 = thi*2, thi*2+1)
    const int arow = tid & 127;
    const int thi  = tid >> 7;
    // X: row = tid (position), 4 x 16B chunks
    int n = nBase + tid;
    if (n >= NDIM) n = NDIM - 1;     // clamp (tail CTA); stores are guarded
    const int b2  = n / P_;
    const int rem = n - b2 * P_;
    const int ho  = rem / W_;
    const int w   = rem - ho * W_;
    const size_t bRowBase = ((size_t)(b2 * 16 + ho) * W_ + w) * C_;

    const __half* aPtr[2];
    uint32_t aSoff[2];
#pragma unroll
    for (int it = 0; it < 2; it++) {
        const int c16 = thi * 2 + it;
        aPtr[it]  = g_wh + (size_t)(mBase + arow) * KDIM + c16 * 8;
        aSoff[it] = (uint32_t)(arow * ROWB + c16 * 16);
    }
    const __half* xPtr = g_xh + bRowBase;
    const uint32_t xSoff = (uint32_t)(TILE_A_B + tid * ROWB);

    // ---- per-warp ldmatrix base addresses (2m x 4n warps, 64x64 tiles) ----
    const int mw = wid >> 2;           // 0..1
    const int nw = wid & 3;            // 0..3
    const uint32_t aAddr = (uint32_t)((mw * 64 + (lane & 15)) * ROWB + ((lane >> 4) << 4));
    const uint32_t bAddr = (uint32_t)(TILE_A_B +
                           (nw * 64 + (lane & 7) + ((lane >> 4) << 3)) * ROWB +
                           (((lane >> 3) & 1) << 4));

    float acc[4][8][4];
#pragma unroll
    for (int i = 0; i < 4; i++)
#pragma unroll
        for (int j = 0; j < 8; j++)
#pragma unroll
            for (int r = 0; r < 4; r++) acc[i][j][r] = 0.f;

    auto issue_chunk = [&](int chunk, uint32_t sbase) {
        const int k0  = chunk << 5;
        const int kh  = k0 >> 9;
        const int ci0 = k0 & 511;
        const size_t bo = (size_t)kh * (W_ * C_) + ci0;
#pragma unroll
        for (int c = 0; c < 2; c++)
            CP_ASYNC16(sbase + aSoff[c], aPtr[c] + k0);
#pragma unroll
        for (int c = 0; c < 4; c++)
            CP_ASYNC16(sbase + xSoff + c * 16, xPtr + bo + c * 8);
    };

    // prologue: stages 0..2 in flight
#pragma unroll
    for (int s = 0; s < STAGES - 1; s++) {
        issue_chunk(s, smb + (uint32_t)s * BUF_B);
        CP_COMMIT();
    }

#pragma unroll 1
    for (int i = 0; i < NCHUNK; i++) {
        CP_WAIT2();              // chunk i resident (2 newer groups outstanding)
        __syncthreads();
        const uint32_t base = smb + (uint32_t)(i & 3) * BUF_B;
#pragma unroll
        for (int q = 0; q < 2; q++) {
            const uint32_t qo = q * 32;
            uint32_t ah[4][4], bf[8][2];
#pragma unroll
            for (int f = 0; f < 4; f++)
                ldsm4(ah[f], base + aAddr + f * 1280 + qo);
#pragma unroll
            for (int t = 0; t < 4; t++) {
                uint32_t r[4];
                ldsm4(r, base + bAddr + t * 1280 + qo);
                bf[2 * t][0] = r[0]; bf[2 * t][1] = r[1];
                bf[2 * t + 1][0] = r[2]; bf[2 * t + 1][1] = r[3];
            }
#pragma unroll
            for (int f = 0; f < 4; f++)
#pragma unroll
                for (int j = 0; j < 8; j++)
                    mma_f16(acc[f][j], ah[f], bf[j]);
        }
        if (i + STAGES - 1 < NCHUNK)
            issue_chunk(i + STAGES - 1, smb + (uint32_t)((i + STAGES - 1) & 3) * BUF_B);
        CP_COMMIT();             // always commit: keeps group count uniform
    }

    // ---- epilogue: bias + relu, fp16 stores (all m < 512), guarded tail ----
    float bias_v[4][2];
#pragma unroll
    for (int f = 0; f < 4; f++)
#pragma unroll
        for (int h = 0; h < 2; h++)
            bias_v[f][h] = g_bias[mBase + mw * 64 + f * 16 + (lane >> 2) + 8 * h];
#pragma unroll
    for (int j = 0; j < 8; j++) {
        const int nj  = nBase + nw * 64 + j * 8 + (lane & 3) * 2;
        if (nj >= NDIM) continue;
        const int bj  = nj / P_;
        const int rj  = nj - bj * P_;
        const size_t fb = (size_t)bj * FEAT_BSTR + rj;
#pragma unroll
        for (int f = 0; f < 4; f++)
#pragma unroll
            for (int h = 0; h < 2; h++) {
                const int m = mBase + mw * 64 + f * 16 + (lane >> 2) + 8 * h;
                __half2 o = __floats2half2_rn(
                    fmaxf(acc[f][j][2 * h]     + bias_v[f][h], 0.f),
                    fmaxf(acc[f][j][2 * h + 1] + bias_v[f][h], 0.f));
                *(__half2*)(g_feats + fb + (size_t)m * P_) = o;
            }
    }
}

// ---------------- K1b: scores GEMM, k-split x4 with atomic merge ----------------
__global__ void __launch_bounds__(128) score_mma() {
    extern __shared__ char sm[];
    const uint32_t smb = smem_u32(sm);
    const int tid  = threadIdx.x;
    const int wid  = tid >> 5;      // 0..3 = n-warp
    const int lane = tid & 31;
    const int nBase = blockIdx.x * SNT;
    const int cBase = blockIdx.y * SCHUNK;     // chunk segment

    // B loader: row = tid, 4 chunks
    const int n   = nBase + tid;
    const int b2  = n / P_;
    const int rem = n - b2 * P_;
    const int ho  = rem / W_;
    const int w   = rem - ho * W_;
    const size_t bRowBase = ((size_t)(b2 * 16 + ho) * W_ + w) * C_;
    // A loader: 64 transfers: 16 rows * 4 chunks (tid < 64)
    const int arow = (tid & 63) >> 2;
    const int ac16 = tid & 3;
    const bool aact = tid < 64;
    const __half* aPtr = g_wh + (size_t)(512 + arow) * KDIM + ac16 * 8;
    const uint32_t aSoff = (uint32_t)(arow * ROWB + ac16 * 16);

    const uint32_t aAddr = (uint32_t)((lane & 15) * ROWB + ((lane >> 4) << 4));
    const uint32_t bAddr = (uint32_t)(S_ATILE +
                           (wid * 32 + (lane & 7) + ((lane >> 4) << 3)) * ROWB +
                           (((lane >> 3) & 1) << 4));

    float acc[4][4];
#pragma unroll
    for (int j = 0; j < 4; j++)
#pragma unroll
        for (int r = 0; r < 4; r++) acc[j][r] = 0.f;

    // prologue: chunk cBase
    {
        const int k0  = cBase << 5;
        const int kh  = k0 >> 9;
        const int ci0 = k0 & 511;
        const size_t bo = (size_t)kh * (W_ * C_) + ci0;
        uint4 vb[4];
#pragma unroll
        for (int c = 0; c < 4; c++) vb[c] = *(const uint4*)(g_xh + bRowBase + bo + c * 8);
        if (aact) *(uint4*)(sm + aSoff) = *(const uint4*)(aPtr + k0);
#pragma unroll
        for (int c = 0; c < 4; c++)
            *(uint4*)(sm + S_ATILE + tid * ROWB + c * 16) = vb[c];
    }
    __syncthreads();

#pragma unroll 1
    for (int i = 0; i < SCHUNK; i++) {
        const int cur = i & 1;
        uint4 va, vb[4];
        const bool hasNext = (i + 1) < SCHUNK;
        if (hasNext) {
            const int k0  = (cBase + i + 1) << 5;
            const int kh  = k0 >> 9;
            const int ci0 = k0 & 511;
            const size_t bo = (size_t)kh * (W_ * C_) + ci0;
            if (aact) va = *(const uint4*)(aPtr + k0);
#pragma unroll
            for (int c = 0; c < 4; c++) vb[c] = *(const uint4*)(g_xh + bRowBase + bo + c * 8);
        }
        {
            const uint32_t base = smb + (uint32_t)cur * S_BUF;
#pragma unroll
            for (int q = 0; q < 2; q++) {
                const uint32_t qo = q * 32;
                uint32_t ah[4], bf[4][2];
                ldsm4(ah, base + aAddr + qo);
#pragma unroll
                for (int t = 0; t < 2; t++) {
                    uint32_t r[4];
                    ldsm4(r, base + bAddr + t * 1280 + qo);
                    bf[2 * t][0] = r[0]; bf[2 * t][1] = r[1];
                    bf[2 * t + 1][0] = r[2]; bf[2 * t + 1][1] = r[3];
                }
#pragma unroll
                for (int j = 0; j < 4; j++)
                    mma_f16(acc[j], ah, bf[j]);
            }
        }
        if (hasNext) {
            char* bb = sm + (cur ^ 1) * S_BUF;
            if (aact) *(uint4*)(bb + aSoff) = va;
#pragma unroll
            for (int c = 0; c < 4; c++)
                *(uint4*)(bb + S_ATILE + tid * ROWB + c * 16) = vb[c];
        }
        __syncthreads();
    }

    // epilogue: rows 0..9 real -> atomic merge into scores
#pragma unroll
    for (int j = 0; j < 4; j++) {
        const int nj  = nBase + wid * 32 + j * 8 + (lane & 3) * 2;
        const int bj  = nj / P_;
        const int rj  = nj - bj * P_;
        const size_t sb = (size_t)bj * SCOR_BSTR + rj;
#pragma unroll
        for (int h = 0; h < 2; h++) {
            const int m = (lane >> 2) + 8 * h;
            if (m < KG_) {
                atomicAdd(g_scores + sb + (size_t)m * P_,     acc[j][2 * h]);
                atomicAdd(g_scores + sb + (size_t)m * P_ + 1, acc[j][2 * h + 1]);
            }
        }
    }
}

// ---------------- K2: softmax over 10 cluster channels ----------------
__global__ void softmax_kernel() {
    int q = blockIdx.x * 256 + threadIdx.x;
    if (q >= NDIM) return;
    int b = q / P_;
    int rem = q - b * P_;
    int base = b * SCOR_BSTR + rem;
    float s[KG_];
    float mx = -1e30f;
#pragma unroll
    for (int k = 0; k < KG_; k++) { s[k] = g_scores[base + k * P_]; mx = fmaxf(mx, s[k]); }
    float sum = 0.f;
#pragma unroll
    for (int k = 0; k < KG_; k++) { s[k] = expf(s[k] - mx); sum += s[k]; }
    float inv = 1.f / sum;
#pragma unroll
    for (int k = 0; k < KG_; k++) g_assign[base + k * P_] = s[k] * inv;
}

// ---------------- K2b: asum ----------------
__global__ void asum_kernel() {
    int b = blockIdx.x >> 3, k = blockIdx.x & 7;
    const float* a = g_assign + b * SCOR_BSTR + k * P_;
    float s = 0.f;
    for (int i = threadIdx.x; i < P_; i += 256) s += a[i];
    __shared__ float red[256];
    red[threadIdx.x] = s;
    __syncthreads();
    for (int st = 128; st > 0; st >>= 1) {
        if (threadIdx.x < st) red[threadIdx.x] += red[threadIdx.x + st];
        __syncthreads();
    }
    if (threadIdx.x == 0) g_asum[blockIdx.x] = red[0];
}

// ---------------- K3: agg[b][k][c] = sum_p assign[b][k][p]*feats[b][c][p] ----------------
__global__ void agg_kernel() {
    __shared__ float fs[64][65];
    __shared__ float as[8][64];
    const int b = blockIdx.y;
    const int c0 = blockIdx.x * 64;
    const int t = threadIdx.x;
    const int k = t >> 6;
    const int c = t & 63;
    const __half* fb = g_feats + (size_t)b * FEAT_BSTR + (size_t)c0 * P_;
    const float* ab = g_assign + b * SCOR_BSTR;
    float acc0 = 0.f, acc1 = 0.f;
    for (int p0 = 0; p0 < P_; p0 += 64) {
        int pc = P_ - p0; if (pc > 64) pc = 64;
#pragma unroll
        for (int idx = t; idx < 4096; idx += 256) {
            int cc = idx >> 6, pp = idx & 63;
            fs[cc][pp] = (pp < pc) ? __half2float(fb[cc * P_ + p0 + pp]) : 0.f;
        }
#pragma unroll
        for (int idx = t; idx < 512; idx += 256) {
            int kk = idx >> 6, pp = idx & 63;
            as[kk][pp] = (pp < pc) ? ab[kk * P_ + p0 + pp] : 0.f;
        }
        __syncthreads();
#pragma unroll
        for (int p = 0; p < 64; p++) {
            float f = fs[c][p];
            acc0 = fmaf(as[k][p], f, acc0);
            acc1 = fmaf(as[k + 4][p], f, acc1);
        }
        __syncthreads();
    }
    g_agg[b * 4096 + k * 512 + c0 + c] = acc0;
    g_agg[b * 4096 + (k + 4) * 512 + c0 + c] = acc1;
}

// ---------------- K4: residual + L2 normalize ----------------
__global__ void vlad_kernel(const float* __restrict__ centroids) {
    const int b = blockIdx.x >> 3, k = blockIdx.x & 7;
    const int t = threadIdx.x;
    const float asum = g_asum[blockIdx.x];
    const float* aggp = g_agg + b * 4096 + k * 512;
    const float* cen = centroids + k * 512;
    float r0 = aggp[t] - asum * cen[t];
    float r1 = aggp[t + 256] - asum * cen[t + 256];
    __shared__ float red[256];
    red[t] = r0 * r0 + r1 * r1;
    __syncthreads();
    for (int st = 128; st > 0; st >>= 1) {
        if (t < st) red[t] += red[t + st];
        __syncthreads();
    }
    __shared__ float scale_s;
    if (t == 0) scale_s = 1.f / fmaxf(sqrtf(red[0]), 1e-12f);
    __syncthreads();
    float sc = scale_s;
    g_vlad[b * 4096 + k * 512 + t] = r0 * sc;
    g_vlad[b * 4096 + k * 512 + t + 256] = r1 * sc;
}

// ---------------- K5: emb = relu(vlad @ fc_w^T + fc_b) ----------------
__global__ void emb_kernel(const float* __restrict__ fc_w,
                           const float* __restrict__ fc_b,
                           float* __restrict__ out) {
    const int b = blockIdx.y, co = blockIdx.x;
    const float4* v = (const float4*)(g_vlad + b * 4096);
    const float4* wr = (const float4*)(fc_w + (size_t)co * 4096);
    float s = 0.f;
    for (int i = threadIdx.x; i < 1024; i += 128) {
        float4 a = v[i], w4 = wr[i];
        s += a.x * w4.x + a.y * w4.y + a.z * w4.z + a.w * w4.w;
    }
    __shared__ float red[128];
    red[threadIdx.x] = s;
    __syncthreads();
    for (int st = 64; st > 0; st >>= 1) {
        if (threadIdx.x < st) red[threadIdx.x] += red[threadIdx.x + st];
        __syncthreads();
    }
    if (threadIdx.x == 0)
        out[b * 512 + co] = fmaxf(red[0] + fc_b[co], 0.f);
}

// ---------------- K6: logit = emb @ logit_w^T ----------------
__global__ void logit_kernel(const float* __restrict__ emb,
                             const float* __restrict__ lw,
                             float* __restrict__ out) {
    const int b = blockIdx.y, o = blockIdx.x;
    const float4* e = (const float4*)(emb + b * 512);
    const float4* wr = (const float4*)(lw + (size_t)o * 512);
    float s = 0.f;
    for (int i = threadIdx.x; i < 128; i += 64) {
        float4 a = e[i], w4 = wr[i];
        s += a.x * w4.x + a.y * w4.y + a.z * w4.z + a.w * w4.w;
    }
    __shared__ float red[64];
    red[threadIdx.x] = s;
    __syncthreads();
    for (int st = 32; st > 0; st >>= 1) {
        if (threadIdx.x < st) red[threadIdx.x] += red[threadIdx.x + st];
        __syncthreads();
    }
    if (threadIdx.x == 0) out[b * OUT_ + o] = red[0];
}

// ---------------- launch ----------------
extern "C" void kernel_launch(void* const* d_in, const int* in_sizes, int n_in,
                              void* d_out, int out_size) {
    const float* x5        = (const float*)d_in[0];
    const float* conv_w    = (const float*)d_in[5];
    const float* conv_b    = (const float*)d_in[6];
    const float* cc_w      = (const float*)d_in[7];
    const float* cc_b      = (const float*)d_in[8];
    const float* centroids = (const float*)d_in[9];
    const float* fc_w      = (const float*)d_in[10];
    const float* fc_b      = (const float*)d_in[11];
    const float* logit_w   = (const float*)d_in[12];
    float* out = (float*)d_out;

    cudaFuncSetAttribute(conv_mma, cudaFuncAttributeMaxDynamicSharedMemorySize, SMEM_TOTAL);

    pack_kernel<<<(MPAD * KDIM + 255) / 256, 256>>>(conv_w, conv_b, cc_w, cc_b);
    init_scores<<<(B_ * SCOR_BSTR + 255) / 256, 256>>>();
    xt_kernel<<<dim3(160, 256), 256>>>(x5);
    conv_mma<<<dim3((NDIM + NT - 1) / NT, 4), 256, SMEM_TOTAL>>>();
    score_mma<<<dim3(NDIM / SNT, KSPLIT), 128, S_SMEM>>>();
    softmax_kernel<<<(NDIM + 255) / 256, 256>>>();
    asum_kernel<<<B_ * KC_, 256>>>();
    agg_kernel<<<dim3(8, B_), 256>>>();
    vlad_kernel<<<B_ * KC_, 256>>>(centroids);
    emb_kernel<<<dim3(C_, B_), 128>>>(fc_w, fc_b, out);
    logit_kernel<<<dim3(OUT_, B_), 64>>>(out, logit_w, out + B_ * C_);
}